// round 2
// baseline (speedup 1.0000x reference)
#include <cuda_runtime.h>
#include <math.h>

// Problem dims
#define QL 2048
#define CTX 2048
#define HDIM 4096
#define NH 32
#define NKV 8
#define HD 128
#define KVLEN (CTX + QL)          // 4096
#define KVSTRIDE (KVLEN * HD)     // 524288 floats per kv head

// Scratch (allocation-free rule: __device__ globals)
__device__ float g_Q[(size_t)QL * HDIM];              // [s][h*128+d], rope'd
__device__ float g_K[(size_t)NKV * KVLEN * HD];       // [kvh][pos][d], rope'd
__device__ float g_V[(size_t)NKV * KVLEN * HD];       // [kvh][pos][d]
__device__ float g_A[(size_t)QL * HDIM];              // attention out [s][h*128+d]

// ---------------------------------------------------------------------------
// GEMM: C[m,n] = sum_k A[m,k] * W[n,k]   (A: MxK row-major, W: NxK row-major)
// mode 0: C row-major [M,N]
// mode 1: KV layout: col -> head = col>>7, hd = col&127;
//         C[head*KVSTRIDE + (pos0+row)*HD + hd]
// Tile 128x128x16, 256 threads, 8x8 per-thread microtile.
// ---------------------------------------------------------------------------
#define GM 128
#define GN 128
#define GK 16

__global__ __launch_bounds__(256, 2)
void gemm_f32(const float* __restrict__ A, const float* __restrict__ W,
              float* __restrict__ C, int M, int N, int K, int mode, int pos0)
{
    __shared__ float As[GK][GM + 4];
    __shared__ float Ws[GK][GN + 4];

    const int tid = threadIdx.x;
    const int tx = tid & 15;
    const int ty = tid >> 4;
    const int bm = blockIdx.y * GM;
    const int bn = blockIdx.x * GN;

    float acc[8][8];
#pragma unroll
    for (int i = 0; i < 8; i++)
#pragma unroll
        for (int j = 0; j < 8; j++) acc[i][j] = 0.0f;

    for (int k0 = 0; k0 < K; k0 += GK) {
#pragma unroll
        for (int i = 0; i < 2; i++) {
            int idx = tid + i * 256;
            int r  = idx >> 2;            // 0..127
            int kc = (idx & 3) << 2;      // 0,4,8,12
            float4 va = *(const float4*)(A + (size_t)(bm + r) * K + (k0 + kc));
            As[kc + 0][r] = va.x; As[kc + 1][r] = va.y;
            As[kc + 2][r] = va.z; As[kc + 3][r] = va.w;
            float4 vw = *(const float4*)(W + (size_t)(bn + r) * K + (k0 + kc));
            Ws[kc + 0][r] = vw.x; Ws[kc + 1][r] = vw.y;
            Ws[kc + 2][r] = vw.z; Ws[kc + 3][r] = vw.w;
        }
        __syncthreads();

#pragma unroll
        for (int kk = 0; kk < GK; kk++) {
            float a[8], b[8];
            *(float4*)(a)     = *(const float4*)&As[kk][ty * 8];
            *(float4*)(a + 4) = *(const float4*)&As[kk][ty * 8 + 4];
            *(float4*)(b)     = *(const float4*)&Ws[kk][tx * 8];
            *(float4*)(b + 4) = *(const float4*)&Ws[kk][tx * 8 + 4];
#pragma unroll
            for (int i = 0; i < 8; i++)
#pragma unroll
                for (int j = 0; j < 8; j++)
                    acc[i][j] = fmaf(a[i], b[j], acc[i][j]);
        }
        __syncthreads();
    }

    if (mode == 0) {
#pragma unroll
        for (int i = 0; i < 8; i++) {
            int row = bm + ty * 8 + i;
            float* crow = C + (size_t)row * N + bn + tx * 8;
            *(float4*)(crow)     = make_float4(acc[i][0], acc[i][1], acc[i][2], acc[i][3]);
            *(float4*)(crow + 4) = make_float4(acc[i][4], acc[i][5], acc[i][6], acc[i][7]);
        }
    } else {
        // whole 128-wide tile lies in one head (head boundaries at multiples of 128)
        const int head = bn >> 7;
#pragma unroll
        for (int i = 0; i < 8; i++) {
            int row = bm + ty * 8 + i;
            float* dst = C + (size_t)head * KVSTRIDE + (size_t)(pos0 + row) * HD + tx * 8;
            *(float4*)(dst)     = make_float4(acc[i][0], acc[i][1], acc[i][2], acc[i][3]);
            *(float4*)(dst + 4) = make_float4(acc[i][4], acc[i][5], acc[i][6], acc[i][7]);
        }
    }
}

// ---------------------------------------------------------------------------
// RoPE (in place).  rotate_half: out[d] = x[d]*cos[d] + rot[d]*sin[d],
// rot[d] = (d<64) ? -x[d+64] : x[d-64].  Each thread does one (row, half-dim).
// Q rows use position CTX+s; K buffer position p maps directly to cos[p]
// (ctx rows 0..2047 -> pos 0..2047, noise rows 2048..4095 -> pos 2048..4095).
// ---------------------------------------------------------------------------
__global__ void rope_q_kernel(float* __restrict__ Q,
                              const float* __restrict__ cosb,
                              const float* __restrict__ sinb)
{
    int idx = blockIdx.x * blockDim.x + threadIdx.x;   // QL*NH*64
    int hd = idx & 63;
    int t  = idx >> 6;
    int h  = t & (NH - 1);
    int s  = t >> 5;
    int pos = CTX + s;
    float c1 = cosb[(size_t)pos * HD + hd];
    float s1 = sinb[(size_t)pos * HD + hd];
    float c2 = cosb[(size_t)pos * HD + hd + 64];
    float s2 = sinb[(size_t)pos * HD + hd + 64];
    float* p = Q + (size_t)s * HDIM + h * HD;
    float x1 = p[hd];
    float x2 = p[hd + 64];
    p[hd]      = x1 * c1 - x2 * s1;
    p[hd + 64] = x2 * c2 + x1 * s2;
}

__global__ void rope_k_kernel(float* __restrict__ Kb,
                              const float* __restrict__ cosb,
                              const float* __restrict__ sinb)
{
    int idx = blockIdx.x * blockDim.x + threadIdx.x;   // NKV*KVLEN*64
    int hd = idx & 63;
    int t  = idx >> 6;
    int pos = t & (KVLEN - 1);
    int kvh = t >> 12;
    float c1 = cosb[(size_t)pos * HD + hd];
    float s1 = sinb[(size_t)pos * HD + hd];
    float c2 = cosb[(size_t)pos * HD + hd + 64];
    float s2 = sinb[(size_t)pos * HD + hd + 64];
    float* p = Kb + (size_t)kvh * KVSTRIDE + (size_t)pos * HD;
    float x1 = p[hd];
    float x2 = p[hd + 64];
    p[hd]      = x1 * c1 - x2 * s1;
    p[hd + 64] = x2 * c2 + x1 * s2;
}

// ---------------------------------------------------------------------------
// Flash attention, fp32, no mask.  Block = (head, 64-query tile), 256 threads
// as 16x16.  GEMM1: 4x4 scores/thread; GEMM2: 4 queries x 8 dims/thread.
// ---------------------------------------------------------------------------
#define ABM 64
#define ABN 64
#define QS_STRIDE (ABM + 4)      // 68 floats (16B-aligned rows: 272B)
#define VS_STRIDE (HD + 4)       // 132 floats (528B)
#define SM_QS 0
#define SM_KS (SM_QS + HD * QS_STRIDE)
#define SM_VS (SM_KS + HD * QS_STRIDE)
#define SM_PS (SM_VS + ABN * VS_STRIDE)
#define SM_TOTAL_F (SM_PS + ABN * QS_STRIDE)
#define SM_TOTAL_B (SM_TOTAL_F * 4)

__global__ __launch_bounds__(256, 1)
void attn_f32(const float* __restrict__ Q, const float* __restrict__ Kb,
              const float* __restrict__ Vb, float* __restrict__ O)
{
    extern __shared__ float sm[];
    float* Qs = sm + SM_QS;   // [d][q]  transposed
    float* Ks = sm + SM_KS;   // [d][k]  transposed
    float* Vs = sm + SM_VS;   // [k][d]
    float* Ps = sm + SM_PS;   // [k][q]  transposed

    const int tid = threadIdx.x;
    const int tx = tid & 15;
    const int ty = tid >> 4;
    const int h  = blockIdx.y;
    const int q0 = blockIdx.x * ABM;
    const int kvh = h >> 2;                      // GQA: 4 q-heads per kv head
    const float scale = 0.08838834764831845f;    // 1/sqrt(128)

    // Load Q tile (64 x 128), transposed + pre-scaled
#pragma unroll
    for (int i = 0; i < 8; i++) {
        int idx = tid + i * 256;
        int q  = idx >> 5;             // 0..63
        int d4 = (idx & 31) << 2;      // 0..124
        float4 v = *(const float4*)(Q + (size_t)(q0 + q) * HDIM + h * HD + d4);
        Qs[(d4 + 0) * QS_STRIDE + q] = v.x * scale;
        Qs[(d4 + 1) * QS_STRIDE + q] = v.y * scale;
        Qs[(d4 + 2) * QS_STRIDE + q] = v.z * scale;
        Qs[(d4 + 3) * QS_STRIDE + q] = v.w * scale;
    }

    float acc[4][8];
    float l[4], mrow[4];
#pragma unroll
    for (int i = 0; i < 4; i++) {
        l[i] = 0.0f;
        mrow[i] = -1e30f;
#pragma unroll
        for (int d = 0; d < 8; d++) acc[i][d] = 0.0f;
    }

    const float* Kbase = Kb + (size_t)kvh * KVSTRIDE;
    const float* Vbase = Vb + (size_t)kvh * KVSTRIDE;

    for (int kc = 0; kc < KVLEN; kc += ABN) {
        __syncthreads();   // previous GEMM2 done with Vs/Ps before overwrite
#pragma unroll
        for (int i = 0; i < 8; i++) {
            int idx = tid + i * 256;
            int k  = idx >> 5;
            int d4 = (idx & 31) << 2;
            float4 kv = *(const float4*)(Kbase + (size_t)(kc + k) * HD + d4);
            Ks[(d4 + 0) * QS_STRIDE + k] = kv.x;
            Ks[(d4 + 1) * QS_STRIDE + k] = kv.y;
            Ks[(d4 + 2) * QS_STRIDE + k] = kv.z;
            Ks[(d4 + 3) * QS_STRIDE + k] = kv.w;
            float4 vv = *(const float4*)(Vbase + (size_t)(kc + k) * HD + d4);
            *(float4*)&Vs[k * VS_STRIDE + d4] = vv;
        }
        __syncthreads();

        // GEMM1: S = (Q*scale) @ K^T
        float s[4][4];
#pragma unroll
        for (int i = 0; i < 4; i++)
#pragma unroll
            for (int j = 0; j < 4; j++) s[i][j] = 0.0f;

#pragma unroll 8
        for (int d = 0; d < HD; d++) {
            float4 qv = *(const float4*)&Qs[d * QS_STRIDE + ty * 4];
            float4 kv = *(const float4*)&Ks[d * QS_STRIDE + tx * 4];
            float qa[4] = {qv.x, qv.y, qv.z, qv.w};
            float ka[4] = {kv.x, kv.y, kv.z, kv.w};
#pragma unroll
            for (int i = 0; i < 4; i++)
#pragma unroll
                for (int j = 0; j < 4; j++)
                    s[i][j] = fmaf(qa[i], ka[j], s[i][j]);
        }

        // Online softmax (row = query, shared by 16 lanes in x)
#pragma unroll
        for (int i = 0; i < 4; i++) {
            float mloc = fmaxf(fmaxf(s[i][0], s[i][1]), fmaxf(s[i][2], s[i][3]));
#pragma unroll
            for (int o = 8; o >= 1; o >>= 1)
                mloc = fmaxf(mloc, __shfl_xor_sync(0xffffffffu, mloc, o, 16));
            float mnew  = fmaxf(mrow[i], mloc);
            float alpha = __expf(mrow[i] - mnew);
            mrow[i] = mnew;
            float lloc = 0.0f;
#pragma unroll
            for (int j = 0; j < 4; j++) {
                float p = __expf(s[i][j] - mnew);
                Ps[(tx * 4 + j) * QS_STRIDE + ty * 4 + i] = p;
                lloc += p;
            }
#pragma unroll
            for (int o = 8; o >= 1; o >>= 1)
                lloc += __shfl_xor_sync(0xffffffffu, lloc, o, 16);
            l[i] = l[i] * alpha + lloc;
#pragma unroll
            for (int d = 0; d < 8; d++) acc[i][d] *= alpha;
        }
        __syncthreads();

        // GEMM2: acc += P @ V
#pragma unroll 4
        for (int k = 0; k < ABN; k++) {
            float4 pv = *(const float4*)&Ps[k * QS_STRIDE + ty * 4];
            float4 v0 = *(const float4*)&Vs[k * VS_STRIDE + tx * 8];
            float4 v1 = *(const float4*)&Vs[k * VS_STRIDE + tx * 8 + 4];
            float pa[4] = {pv.x, pv.y, pv.z, pv.w};
            float va[8] = {v0.x, v0.y, v0.z, v0.w, v1.x, v1.y, v1.z, v1.w};
#pragma unroll
            for (int i = 0; i < 4; i++)
#pragma unroll
                for (int d = 0; d < 8; d++)
                    acc[i][d] = fmaf(pa[i], va[d], acc[i][d]);
        }
    }

    // Epilogue: normalize and store
#pragma unroll
    for (int i = 0; i < 4; i++) {
        float inv = 1.0f / l[i];
        int row = q0 + ty * 4 + i;
        float* orow = O + (size_t)row * HDIM + h * HD + tx * 8;
        *(float4*)(orow)     = make_float4(acc[i][0] * inv, acc[i][1] * inv,
                                           acc[i][2] * inv, acc[i][3] * inv);
        *(float4*)(orow + 4) = make_float4(acc[i][4] * inv, acc[i][5] * inv,
                                           acc[i][6] * inv, acc[i][7] * inv);
    }
}

// ---------------------------------------------------------------------------
// Launch
// ---------------------------------------------------------------------------
extern "C" void kernel_launch(void* const* d_in, const int* in_sizes, int n_in,
                              void* d_out, int out_size)
{
    (void)in_sizes; (void)n_in; (void)out_size;
    const float* hidden = (const float*)d_in[0];
    const float* target = (const float*)d_in[1];
    const float* cosb   = (const float*)d_in[2];
    const float* sinb   = (const float*)d_in[3];
    const float* Wq     = (const float*)d_in[4];
    const float* Wk     = (const float*)d_in[5];
    const float* Wv     = (const float*)d_in[6];
    const float* Wo     = (const float*)d_in[7];
    float* out = (float*)d_out;

    float *Qp, *Kp, *Vp, *Ap;
    cudaGetSymbolAddress((void**)&Qp, g_Q);
    cudaGetSymbolAddress((void**)&Kp, g_K);
    cudaGetSymbolAddress((void**)&Vp, g_V);
    cudaGetSymbolAddress((void**)&Ap, g_A);

    cudaFuncSetAttribute(attn_f32, cudaFuncAttributeMaxDynamicSharedMemorySize,
                         SM_TOTAL_B);

    dim3 t256(256);

    // Projections
    gemm_f32<<<dim3(HDIM / GN, QL / GM), t256>>>(hidden, Wq, Qp, QL, HDIM, HDIM, 0, 0);
    gemm_f32<<<dim3((NKV * HD) / GN, CTX / GM), t256>>>(target, Wk, Kp, CTX, NKV * HD, HDIM, 1, 0);
    gemm_f32<<<dim3((NKV * HD) / GN, QL / GM), t256>>>(hidden, Wk, Kp, QL, NKV * HD, HDIM, 1, CTX);
    gemm_f32<<<dim3((NKV * HD) / GN, CTX / GM), t256>>>(target, Wv, Vp, CTX, NKV * HD, HDIM, 1, 0);
    gemm_f32<<<dim3((NKV * HD) / GN, QL / GM), t256>>>(hidden, Wv, Vp, QL, NKV * HD, HDIM, 1, CTX);

    // RoPE
    rope_q_kernel<<<(QL * NH * 64) / 256, 256>>>(Qp, cosb, sinb);
    rope_k_kernel<<<(NKV * KVLEN * 64) / 256, 256>>>(Kp, cosb, sinb);

    // Attention
    attn_f32<<<dim3(QL / ABM, NH), t256, SM_TOTAL_B>>>(Qp, Kp, Vp, Ap);

    // Output projection
    gemm_f32<<<dim3(HDIM / GN, QL / GM), t256>>>(Ap, Wo, out, QL, HDIM, HDIM, 0, 0);
}

// round 5
// speedup vs baseline: 1.4360x; 1.4360x over previous
#include <cuda_runtime.h>
#include <cuda_bf16.h>
#include <math.h>
#include <stdint.h>

// Problem dims
#define QL 2048
#define CTX 2048
#define HDIM 4096
#define NH 32
#define NKV 8
#define HD 128
#define KVLEN (CTX + QL)          // 4096
#define KVSTRIDE (KVLEN * HD)     // floats per kv head

// ---------------------------------------------------------------------------
// Scratch (__device__ globals; allocation-free rule)
// ---------------------------------------------------------------------------
__device__ float g_Q[(size_t)QL * HDIM];
__device__ float g_K[(size_t)NKV * KVLEN * HD];
__device__ float g_V[(size_t)NKV * KVLEN * HD];
__device__ float g_A[(size_t)QL * HDIM];

__device__ __nv_bfloat16 g_hidHi[(size_t)QL * HDIM],  g_hidLo[(size_t)QL * HDIM];
__device__ __nv_bfloat16 g_tgtHi[(size_t)CTX * HDIM], g_tgtLo[(size_t)CTX * HDIM];
__device__ __nv_bfloat16 g_WqHi[(size_t)HDIM * HDIM], g_WqLo[(size_t)HDIM * HDIM];
__device__ __nv_bfloat16 g_WkHi[(size_t)NKV * HD * HDIM], g_WkLo[(size_t)NKV * HD * HDIM];
__device__ __nv_bfloat16 g_WvHi[(size_t)NKV * HD * HDIM], g_WvLo[(size_t)NKV * HD * HDIM];
__device__ __nv_bfloat16 g_WoHi[(size_t)HDIM * HDIM], g_WoLo[(size_t)HDIM * HDIM];
__device__ __nv_bfloat16 g_AHi[(size_t)QL * HDIM],  g_ALo[(size_t)QL * HDIM];

// ---------------------------------------------------------------------------
// PTX helpers (base sm_103-legal only: cp.async, ldmatrix, mma.sync)
// ---------------------------------------------------------------------------
__device__ __forceinline__ uint32_t smem_u32(const void* p) {
    uint32_t a;
    asm("{ .reg .u64 t; cvta.to.shared.u64 t, %1; cvt.u32.u64 %0, t; }" : "=r"(a) : "l"(p));
    return a;
}
#define CP_ASYNC16(dst, src) \
    asm volatile("cp.async.cg.shared.global [%0], [%1], 16;" :: "r"(dst), "l"(src))
#define CP_COMMIT() asm volatile("cp.async.commit_group;" ::: "memory")
#define CP_WAIT1()  asm volatile("cp.async.wait_group 1;" ::: "memory")

#define LDSM_X4(r0, r1, r2, r3, addr) \
    asm volatile("ldmatrix.sync.aligned.m8n8.x4.shared.b16 {%0,%1,%2,%3}, [%4];" \
                 : "=r"(r0), "=r"(r1), "=r"(r2), "=r"(r3) : "r"(addr))

#define MMA16816(d, a, b) \
    asm volatile("mma.sync.aligned.m16n8k16.row.col.f32.bf16.bf16.f32 " \
                 "{%0,%1,%2,%3}, {%4,%5,%6,%7}, {%8,%9}, {%0,%1,%2,%3};" \
                 : "+f"((d)[0]), "+f"((d)[1]), "+f"((d)[2]), "+f"((d)[3]) \
                 : "r"((a)[0]), "r"((a)[1]), "r"((a)[2]), "r"((a)[3]), \
                   "r"((b)[0]), "r"((b)[1]))

// ---------------------------------------------------------------------------
// bf16-split HMMA GEMM: C[M,N] = A[M,K] * W[N,K]^T  (fp32-grade: hh+hl+lh)
// Tile 128x128, K-chunk 32, 256 threads, double-buffered cp.async.
// Warp (wid): rows [wid>>2]*64, cols [wid&3]*32; 4x4 m16n8k16 tiles.
// mode 0: C row-major [., ldn];  mode 1: KV layout C[head][pos0+row][hd].
// ---------------------------------------------------------------------------
#define TM 128
#define TN 128
#define TK 32
#define ASTRIDE 40                       // bf16 per smem row (32 data + 8 pad)
#define TILE_B (128 * ASTRIDE * 2)       // 10240 bytes
#define OFF_ALO TILE_B
#define OFF_BHI (2 * TILE_B)
#define OFF_BLO (3 * TILE_B)
#define STG_B (4 * TILE_B)               // 40960 bytes per stage
#define SMEM_G (2 * STG_B)               // 81920 bytes

__device__ __forceinline__ void g_load_stage(
    uint32_t sb, int stage, int tid,
    const __nv_bfloat16* aHi, const __nv_bfloat16* aLo,
    const __nv_bfloat16* bHi, const __nv_bfloat16* bLo,
    int bm, int bn, int K, int k0)
{
    const uint32_t st = sb + stage * STG_B;
#pragma unroll
    for (int t = 0; t < 8; t++) {
        int idx = tid + 256 * t;          // 0..2047
        int tile = idx >> 9;              // 0..3
        int rem = idx & 511;
        int r = rem >> 2;
        int c = rem & 3;
        const __nv_bfloat16* base;
        int grow;
        if (tile == 0)      { base = aHi; grow = bm + r; }
        else if (tile == 1) { base = aLo; grow = bm + r; }
        else if (tile == 2) { base = bHi; grow = bn + r; }
        else                { base = bLo; grow = bn + r; }
        const char* src = (const char*)(base + (size_t)grow * K + k0 + c * 8);
        uint32_t dst = st + tile * TILE_B + (r * ASTRIDE + c * 8) * 2;
        CP_ASYNC16(dst, src);
    }
}

__global__ __launch_bounds__(256, 1)
void gemm_mma(const __nv_bfloat16* __restrict__ aHi, const __nv_bfloat16* __restrict__ aLo,
              const __nv_bfloat16* __restrict__ bHi, const __nv_bfloat16* __restrict__ bLo,
              float* __restrict__ C, int K, int ldn, int mode, int pos0)
{
    extern __shared__ char smem[];
    const uint32_t sb = smem_u32(smem);
    const int tid = threadIdx.x;
    const int wid = tid >> 5;
    const int lane = tid & 31;
    const int bm = blockIdx.y * TM;
    const int bn = blockIdx.x * TN;
    const int wm = (wid >> 2) * 64;
    const int wn = (wid & 3) * 32;
    const int nch = K / TK;

    float acc[4][4][4];
#pragma unroll
    for (int mt = 0; mt < 4; mt++)
#pragma unroll
        for (int nt = 0; nt < 4; nt++)
#pragma unroll
            for (int i = 0; i < 4; i++) acc[mt][nt][i] = 0.0f;

    g_load_stage(sb, 0, tid, aHi, aLo, bHi, bLo, bm, bn, K, 0);
    CP_COMMIT();

    for (int c = 0; c < nch; c++) {
        if (c + 1 < nch)
            g_load_stage(sb, (c + 1) & 1, tid, aHi, aLo, bHi, bLo, bm, bn, K, (c + 1) * TK);
        CP_COMMIT();
        CP_WAIT1();
        __syncthreads();

        const uint32_t st = sb + (c & 1) * STG_B;
#pragma unroll
        for (int kg = 0; kg < 2; kg++) {
            uint32_t ah[4][4], al[4][4], bh[2][4], bl[2][4];
            const int acol = kg * 16 + (lane >> 4) * 8;
#pragma unroll
            for (int mt = 0; mt < 4; mt++) {
                int row = wm + mt * 16 + (lane & 15);
                uint32_t ad = st + (row * ASTRIDE + acol) * 2;
                LDSM_X4(ah[mt][0], ah[mt][1], ah[mt][2], ah[mt][3], ad);
                LDSM_X4(al[mt][0], al[mt][1], al[mt][2], al[mt][3], ad + OFF_ALO);
            }
            const int bcol = kg * 16 + ((lane >> 3) & 1) * 8;
#pragma unroll
            for (int p = 0; p < 2; p++) {
                int brow = wn + p * 16 + (lane & 7) + (lane >> 4) * 8;
                uint32_t bd = st + OFF_BHI + (brow * ASTRIDE + bcol) * 2;
                LDSM_X4(bh[p][0], bh[p][1], bh[p][2], bh[p][3], bd);
                LDSM_X4(bl[p][0], bl[p][1], bl[p][2], bl[p][3], bd + TILE_B);
            }
#pragma unroll
            for (int mt = 0; mt < 4; mt++)
#pragma unroll
                for (int nt = 0; nt < 4; nt++) {
                    const int p = nt >> 1, q = (nt & 1) * 2;
                    MMA16816(acc[mt][nt], ah[mt], &bh[p][q]);   // hi*hi
                    MMA16816(acc[mt][nt], ah[mt], &bl[p][q]);   // hi*lo
                    MMA16816(acc[mt][nt], al[mt], &bh[p][q]);   // lo*hi
                }
        }
        __syncthreads();
    }

    // Epilogue
#pragma unroll
    for (int mt = 0; mt < 4; mt++)
#pragma unroll
        for (int nt = 0; nt < 4; nt++) {
            int row = bm + wm + mt * 16 + (lane >> 2);
            int col = bn + wn + nt * 8 + (lane & 3) * 2;
            float2 v0 = make_float2(acc[mt][nt][0], acc[mt][nt][1]);
            float2 v1 = make_float2(acc[mt][nt][2], acc[mt][nt][3]);
            if (mode == 0) {
                *(float2*)(C + (size_t)row * ldn + col) = v0;
                *(float2*)(C + (size_t)(row + 8) * ldn + col) = v1;
            } else {
                const int head = col >> 7;
                const int hd = col & 127;
                float* base = C + (size_t)head * KVSTRIDE + hd;
                *(float2*)(base + (size_t)(pos0 + row) * HD) = v0;
                *(float2*)(base + (size_t)(pos0 + row + 8) * HD) = v1;
            }
        }
}

// ---------------------------------------------------------------------------
// fp32 -> (bf16 hi, bf16 lo) split
// ---------------------------------------------------------------------------
__global__ void cvt_split(const float4* __restrict__ x,
                          __nv_bfloat162* __restrict__ hi,
                          __nv_bfloat162* __restrict__ lo, int n4)
{
    int i = blockIdx.x * blockDim.x + threadIdx.x;
    if (i >= n4) return;
    float4 v = x[i];
    __nv_bfloat16 hx = __float2bfloat16_rn(v.x);
    __nv_bfloat16 hy = __float2bfloat16_rn(v.y);
    __nv_bfloat16 hz = __float2bfloat16_rn(v.z);
    __nv_bfloat16 hw = __float2bfloat16_rn(v.w);
    __nv_bfloat16 lx = __float2bfloat16_rn(v.x - __bfloat162float(hx));
    __nv_bfloat16 ly = __float2bfloat16_rn(v.y - __bfloat162float(hy));
    __nv_bfloat16 lz = __float2bfloat16_rn(v.z - __bfloat162float(hz));
    __nv_bfloat16 lw = __float2bfloat16_rn(v.w - __bfloat162float(hw));
    hi[2 * i + 0] = __halves2bfloat162(hx, hy);
    hi[2 * i + 1] = __halves2bfloat162(hz, hw);
    lo[2 * i + 0] = __halves2bfloat162(lx, ly);
    lo[2 * i + 1] = __halves2bfloat162(lz, lw);
}

// ---------------------------------------------------------------------------
// RoPE
// ---------------------------------------------------------------------------
__global__ void rope_q_kernel(float* __restrict__ Q,
                              const float* __restrict__ cosb,
                              const float* __restrict__ sinb)
{
    int idx = blockIdx.x * blockDim.x + threadIdx.x;
    int hd = idx & 63;
    int t  = idx >> 6;
    int h  = t & (NH - 1);
    int s  = t >> 5;
    int pos = CTX + s;
    float c1 = cosb[(size_t)pos * HD + hd];
    float s1 = sinb[(size_t)pos * HD + hd];
    float c2 = cosb[(size_t)pos * HD + hd + 64];
    float s2 = sinb[(size_t)pos * HD + hd + 64];
    float* p = Q + (size_t)s * HDIM + h * HD;
    float x1 = p[hd];
    float x2 = p[hd + 64];
    p[hd]      = x1 * c1 - x2 * s1;
    p[hd + 64] = x2 * c2 + x1 * s2;
}

__global__ void rope_k_kernel(float* __restrict__ Kb,
                              const float* __restrict__ cosb,
                              const float* __restrict__ sinb)
{
    int idx = blockIdx.x * blockDim.x + threadIdx.x;
    int hd = idx & 63;
    int t  = idx >> 6;
    int pos = t & (KVLEN - 1);
    int kvh = t >> 12;
    float c1 = cosb[(size_t)pos * HD + hd];
    float s1 = sinb[(size_t)pos * HD + hd];
    float c2 = cosb[(size_t)pos * HD + hd + 64];
    float s2 = sinb[(size_t)pos * HD + hd + 64];
    float* p = Kb + (size_t)kvh * KVSTRIDE + (size_t)pos * HD;
    float x1 = p[hd];
    float x2 = p[hd + 64];
    p[hd]      = x1 * c1 - x2 * s1;
    p[hd + 64] = x2 * c2 + x1 * s2;
}

// ---------------------------------------------------------------------------
// Flash attention, fp32 SIMT (known-good from R1)
// ---------------------------------------------------------------------------
#define ABM 64
#define ABN 64
#define QS_STRIDE (ABM + 4)
#define VS_STRIDE (HD + 4)
#define SM_QS 0
#define SM_KS (SM_QS + HD * QS_STRIDE)
#define SM_VS (SM_KS + HD * QS_STRIDE)
#define SM_PS (SM_VS + ABN * VS_STRIDE)
#define SM_TOTAL_F (SM_PS + ABN * QS_STRIDE)
#define SM_TOTAL_B (SM_TOTAL_F * 4)

__global__ __launch_bounds__(256, 1)
void attn_f32(const float* __restrict__ Q, const float* __restrict__ Kb,
              const float* __restrict__ Vb, float* __restrict__ O)
{
    extern __shared__ float sm[];
    float* Qs = sm + SM_QS;
    float* Ks = sm + SM_KS;
    float* Vs = sm + SM_VS;
    float* Ps = sm + SM_PS;

    const int tid = threadIdx.x;
    const int tx = tid & 15;
    const int ty = tid >> 4;
    const int h  = blockIdx.y;
    const int q0 = blockIdx.x * ABM;
    const int kvh = h >> 2;
    const float scale = 0.08838834764831845f;

#pragma unroll
    for (int i = 0; i < 8; i++) {
        int idx = tid + i * 256;
        int q  = idx >> 5;
        int d4 = (idx & 31) << 2;
        float4 v = *(const float4*)(Q + (size_t)(q0 + q) * HDIM + h * HD + d4);
        Qs[(d4 + 0) * QS_STRIDE + q] = v.x * scale;
        Qs[(d4 + 1) * QS_STRIDE + q] = v.y * scale;
        Qs[(d4 + 2) * QS_STRIDE + q] = v.z * scale;
        Qs[(d4 + 3) * QS_STRIDE + q] = v.w * scale;
    }

    float acc[4][8];
    float l[4], mrow[4];
#pragma unroll
    for (int i = 0; i < 4; i++) {
        l[i] = 0.0f;
        mrow[i] = -1e30f;
#pragma unroll
        for (int d = 0; d < 8; d++) acc[i][d] = 0.0f;
    }

    const float* Kbase = Kb + (size_t)kvh * KVSTRIDE;
    const float* Vbase = Vb + (size_t)kvh * KVSTRIDE;

    for (int kc = 0; kc < KVLEN; kc += ABN) {
        __syncthreads();
#pragma unroll
        for (int i = 0; i < 8; i++) {
            int idx = tid + i * 256;
            int k  = idx >> 5;
            int d4 = (idx & 31) << 2;
            float4 kv = *(const float4*)(Kbase + (size_t)(kc + k) * HD + d4);
            Ks[(d4 + 0) * QS_STRIDE + k] = kv.x;
            Ks[(d4 + 1) * QS_STRIDE + k] = kv.y;
            Ks[(d4 + 2) * QS_STRIDE + k] = kv.z;
            Ks[(d4 + 3) * QS_STRIDE + k] = kv.w;
            float4 vv = *(const float4*)(Vbase + (size_t)(kc + k) * HD + d4);
            *(float4*)&Vs[k * VS_STRIDE + d4] = vv;
        }
        __syncthreads();

        float s[4][4];
#pragma unroll
        for (int i = 0; i < 4; i++)
#pragma unroll
            for (int j = 0; j < 4; j++) s[i][j] = 0.0f;

#pragma unroll 8
        for (int d = 0; d < HD; d++) {
            float4 qv = *(const float4*)&Qs[d * QS_STRIDE + ty * 4];
            float4 kv = *(const float4*)&Ks[d * QS_STRIDE + tx * 4];
            float qa[4] = {qv.x, qv.y, qv.z, qv.w};
            float ka[4] = {kv.x, kv.y, kv.z, kv.w};
#pragma unroll
            for (int i = 0; i < 4; i++)
#pragma unroll
                for (int j = 0; j < 4; j++)
                    s[i][j] = fmaf(qa[i], ka[j], s[i][j]);
        }

#pragma unroll
        for (int i = 0; i < 4; i++) {
            float mloc = fmaxf(fmaxf(s[i][0], s[i][1]), fmaxf(s[i][2], s[i][3]));
#pragma unroll
            for (int o = 8; o >= 1; o >>= 1)
                mloc = fmaxf(mloc, __shfl_xor_sync(0xffffffffu, mloc, o, 16));
            float mnew  = fmaxf(mrow[i], mloc);
            float alpha = __expf(mrow[i] - mnew);
            mrow[i] = mnew;
            float lloc = 0.0f;
#pragma unroll
            for (int j = 0; j < 4; j++) {
                float p = __expf(s[i][j] - mnew);
                Ps[(tx * 4 + j) * QS_STRIDE + ty * 4 + i] = p;
                lloc += p;
            }
#pragma unroll
            for (int o = 8; o >= 1; o >>= 1)
                lloc += __shfl_xor_sync(0xffffffffu, lloc, o, 16);
            l[i] = l[i] * alpha + lloc;
#pragma unroll
            for (int d = 0; d < 8; d++) acc[i][d] *= alpha;
        }
        __syncthreads();

#pragma unroll 4
        for (int k = 0; k < ABN; k++) {
            float4 pv = *(const float4*)&Ps[k * QS_STRIDE + ty * 4];
            float4 v0 = *(const float4*)&Vs[k * VS_STRIDE + tx * 8];
            float4 v1 = *(const float4*)&Vs[k * VS_STRIDE + tx * 8 + 4];
            float pa[4] = {pv.x, pv.y, pv.z, pv.w};
            float va[8] = {v0.x, v0.y, v0.z, v0.w, v1.x, v1.y, v1.z, v1.w};
#pragma unroll
            for (int i = 0; i < 4; i++)
#pragma unroll
                for (int d = 0; d < 8; d++)
                    acc[i][d] = fmaf(pa[i], va[d], acc[i][d]);
        }
    }

#pragma unroll
    for (int i = 0; i < 4; i++) {
        float inv = 1.0f / l[i];
        int row = q0 + ty * 4 + i;
        float* orow = O + (size_t)row * HDIM + h * HD + tx * 8;
        *(float4*)(orow)     = make_float4(acc[i][0] * inv, acc[i][1] * inv,
                                           acc[i][2] * inv, acc[i][3] * inv);
        *(float4*)(orow + 4) = make_float4(acc[i][4] * inv, acc[i][5] * inv,
                                           acc[i][6] * inv, acc[i][7] * inv);
    }
}

// ---------------------------------------------------------------------------
// Launch
// ---------------------------------------------------------------------------
extern "C" void kernel_launch(void* const* d_in, const int* in_sizes, int n_in,
                              void* d_out, int out_size)
{
    (void)in_sizes; (void)n_in; (void)out_size;
    const float* hidden = (const float*)d_in[0];
    const float* target = (const float*)d_in[1];
    const float* cosb   = (const float*)d_in[2];
    const float* sinb   = (const float*)d_in[3];
    float* out = (float*)d_out;

    float *Qp, *Kp, *Vp, *Ap;
    cudaGetSymbolAddress((void**)&Qp, g_Q);
    cudaGetSymbolAddress((void**)&Kp, g_K);
    cudaGetSymbolAddress((void**)&Vp, g_V);
    cudaGetSymbolAddress((void**)&Ap, g_A);

    __nv_bfloat16 *hidHi, *hidLo, *tgtHi, *tgtLo, *WqHi, *WqLo, *WkHi, *WkLo,
                  *WvHi, *WvLo, *WoHi, *WoLo, *AHi, *ALo;
    cudaGetSymbolAddress((void**)&hidHi, g_hidHi);
    cudaGetSymbolAddress((void**)&hidLo, g_hidLo);
    cudaGetSymbolAddress((void**)&tgtHi, g_tgtHi);
    cudaGetSymbolAddress((void**)&tgtLo, g_tgtLo);
    cudaGetSymbolAddress((void**)&WqHi, g_WqHi);
    cudaGetSymbolAddress((void**)&WqLo, g_WqLo);
    cudaGetSymbolAddress((void**)&WkHi, g_WkHi);
    cudaGetSymbolAddress((void**)&WkLo, g_WkLo);
    cudaGetSymbolAddress((void**)&WvHi, g_WvHi);
    cudaGetSymbolAddress((void**)&WvLo, g_WvLo);
    cudaGetSymbolAddress((void**)&WoHi, g_WoHi);
    cudaGetSymbolAddress((void**)&WoLo, g_WoLo);
    cudaGetSymbolAddress((void**)&AHi, g_AHi);
    cudaGetSymbolAddress((void**)&ALo, g_ALo);

    cudaFuncSetAttribute(gemm_mma, cudaFuncAttributeMaxDynamicSharedMemorySize, SMEM_G);
    cudaFuncSetAttribute(attn_f32, cudaFuncAttributeMaxDynamicSharedMemorySize, SM_TOTAL_B);

    // fp32 -> bf16 hi/lo splits
    {
        int n;
        n = QL * HDIM;
        cvt_split<<<n / 4 / 256, 256>>>((const float4*)hidden, (__nv_bfloat162*)hidHi, (__nv_bfloat162*)hidLo, n / 4);
        n = CTX * HDIM;
        cvt_split<<<n / 4 / 256, 256>>>((const float4*)target, (__nv_bfloat162*)tgtHi, (__nv_bfloat162*)tgtLo, n / 4);
        n = HDIM * HDIM;
        cvt_split<<<n / 4 / 256, 256>>>((const float4*)d_in[4], (__nv_bfloat162*)WqHi, (__nv_bfloat162*)WqLo, n / 4);
        n = NKV * HD * HDIM;
        cvt_split<<<n / 4 / 256, 256>>>((const float4*)d_in[5], (__nv_bfloat162*)WkHi, (__nv_bfloat162*)WkLo, n / 4);
        cvt_split<<<n / 4 / 256, 256>>>((const float4*)d_in[6], (__nv_bfloat162*)WvHi, (__nv_bfloat162*)WvLo, n / 4);
        n = HDIM * HDIM;
        cvt_split<<<n / 4 / 256, 256>>>((const float4*)d_in[7], (__nv_bfloat162*)WoHi, (__nv_bfloat162*)WoLo, n / 4);
    }

    // Projections (HMMA, bf16 3-pass split)
    gemm_mma<<<dim3(HDIM / TN, QL / TM), 256, SMEM_G>>>(hidHi, hidLo, WqHi, WqLo, Qp, HDIM, HDIM, 0, 0);
    gemm_mma<<<dim3((NKV * HD) / TN, CTX / TM), 256, SMEM_G>>>(tgtHi, tgtLo, WkHi, WkLo, Kp, HDIM, 0, 1, 0);
    gemm_mma<<<dim3((NKV * HD) / TN, QL / TM), 256, SMEM_G>>>(hidHi, hidLo, WkHi, WkLo, Kp, HDIM, 0, 1, CTX);
    gemm_mma<<<dim3((NKV * HD) / TN, CTX / TM), 256, SMEM_G>>>(tgtHi, tgtLo, WvHi, WvLo, Vp, HDIM, 0, 1, 0);
    gemm_mma<<<dim3((NKV * HD) / TN, QL / TM), 256, SMEM_G>>>(hidHi, hidLo, WvHi, WvLo, Vp, HDIM, 0, 1, CTX);

    // RoPE
    rope_q_kernel<<<(QL * NH * 64) / 256, 256>>>(Qp, cosb, sinb);
    rope_k_kernel<<<(NKV * KVLEN * 64) / 256, 256>>>(Kp, cosb, sinb);

    // Attention (fp32 SIMT)
    attn_f32<<<dim3(QL / ABM, NH), 256, SM_TOTAL_B>>>(Qp, Kp, Vp, Ap);

    // Output projection
    {
        int n = QL * HDIM;
        cvt_split<<<n / 4 / 256, 256>>>((const float4*)Ap, (__nv_bfloat162*)AHi, (__nv_bfloat162*)ALo, n / 4);
    }
    gemm_mma<<<dim3(HDIM / TN, QL / TM), 256, SMEM_G>>>(AHi, ALo, WoHi, WoLo, out, HDIM, HDIM, 0, 0);
}

// round 6
// speedup vs baseline: 3.1263x; 2.1772x over previous
#include <cuda_runtime.h>
#include <cuda_bf16.h>
#include <math.h>
#include <stdint.h>

// Problem dims
#define QL 2048
#define CTX 2048
#define HDIM 4096
#define NH 32
#define NKV 8
#define HD 128
#define KVLEN (CTX + QL)          // 4096
#define KVSTRIDE (KVLEN * HD)     // elements per kv head

#define QSCALE (0.08838834764831845f * 1.4426950408889634f)   // (1/sqrt(128))*log2(e)

// ---------------------------------------------------------------------------
// Scratch (__device__ globals; allocation-free rule)
// ---------------------------------------------------------------------------
__device__ float g_Q[(size_t)QL * HDIM];
__device__ float g_K[(size_t)NKV * KVLEN * HD];
__device__ float g_V[(size_t)NKV * KVLEN * HD];

__device__ __nv_bfloat16 g_hidHi[(size_t)QL * HDIM],  g_hidLo[(size_t)QL * HDIM];
__device__ __nv_bfloat16 g_tgtHi[(size_t)CTX * HDIM], g_tgtLo[(size_t)CTX * HDIM];
__device__ __nv_bfloat16 g_WqHi[(size_t)HDIM * HDIM], g_WqLo[(size_t)HDIM * HDIM];
__device__ __nv_bfloat16 g_WkHi[(size_t)NKV * HD * HDIM], g_WkLo[(size_t)NKV * HD * HDIM];
__device__ __nv_bfloat16 g_WvHi[(size_t)NKV * HD * HDIM], g_WvLo[(size_t)NKV * HD * HDIM];
__device__ __nv_bfloat16 g_WoHi[(size_t)HDIM * HDIM], g_WoLo[(size_t)HDIM * HDIM];
__device__ __nv_bfloat16 g_AHi[(size_t)QL * HDIM],  g_ALo[(size_t)QL * HDIM];

__device__ __nv_bfloat16 g_Qh[(size_t)QL * HDIM],  g_Ql[(size_t)QL * HDIM];
__device__ __nv_bfloat16 g_Kh[(size_t)NKV * KVLEN * HD], g_Kl[(size_t)NKV * KVLEN * HD];
__device__ __nv_bfloat16 g_Vh[(size_t)NKV * KVLEN * HD], g_Vl[(size_t)NKV * KVLEN * HD];

// ---------------------------------------------------------------------------
// PTX helpers (base sm_103-legal only: cp.async, ldmatrix, mma.sync)
// ---------------------------------------------------------------------------
__device__ __forceinline__ uint32_t smem_u32(const void* p) {
    uint32_t a;
    asm("{ .reg .u64 t; cvta.to.shared.u64 t, %1; cvt.u32.u64 %0, t; }" : "=r"(a) : "l"(p));
    return a;
}
#define CP_ASYNC16(dst, src) \
    asm volatile("cp.async.cg.shared.global [%0], [%1], 16;" :: "r"(dst), "l"(src))
#define CP_COMMIT() asm volatile("cp.async.commit_group;" ::: "memory")
#define CP_WAIT1()  asm volatile("cp.async.wait_group 1;" ::: "memory")

#define LDSM_X4(r0, r1, r2, r3, addr) \
    asm volatile("ldmatrix.sync.aligned.m8n8.x4.shared.b16 {%0,%1,%2,%3}, [%4];" \
                 : "=r"(r0), "=r"(r1), "=r"(r2), "=r"(r3) : "r"(addr))
#define LDSM_X4_T(r0, r1, r2, r3, addr) \
    asm volatile("ldmatrix.sync.aligned.m8n8.x4.trans.shared.b16 {%0,%1,%2,%3}, [%4];" \
                 : "=r"(r0), "=r"(r1), "=r"(r2), "=r"(r3) : "r"(addr))

#define MMA16816(d, a, b) \
    asm volatile("mma.sync.aligned.m16n8k16.row.col.f32.bf16.bf16.f32 " \
                 "{%0,%1,%2,%3}, {%4,%5,%6,%7}, {%8,%9}, {%0,%1,%2,%3};" \
                 : "+f"((d)[0]), "+f"((d)[1]), "+f"((d)[2]), "+f"((d)[3]) \
                 : "r"((a)[0]), "r"((a)[1]), "r"((a)[2]), "r"((a)[3]), \
                   "r"((b)[0]), "r"((b)[1]))

// pack (lo, hi) floats into bf16x2
#define PACK_BF16X2(r, flo, fhi) \
    asm("cvt.rn.bf16x2.f32 %0, %1, %2;" : "=r"(r) : "f"(fhi), "f"(flo))

// ---------------------------------------------------------------------------
// bf16-split HMMA GEMM (passing R4 version, unchanged)
// ---------------------------------------------------------------------------
#define TM 128
#define TN 128
#define TK 32
#define ASTRIDE 40
#define TILE_B (128 * ASTRIDE * 2)
#define OFF_ALO TILE_B
#define OFF_BHI (2 * TILE_B)
#define OFF_BLO (3 * TILE_B)
#define STG_B (4 * TILE_B)
#define SMEM_G (2 * STG_B)

__device__ __forceinline__ void g_load_stage(
    uint32_t sb, int stage, int tid,
    const __nv_bfloat16* aHi, const __nv_bfloat16* aLo,
    const __nv_bfloat16* bHi, const __nv_bfloat16* bLo,
    int bm, int bn, int K, int k0)
{
    const uint32_t st = sb + stage * STG_B;
#pragma unroll
    for (int t = 0; t < 8; t++) {
        int idx = tid + 256 * t;
        int tile = idx >> 9;
        int rem = idx & 511;
        int r = rem >> 2;
        int c = rem & 3;
        const __nv_bfloat16* base;
        int grow;
        if (tile == 0)      { base = aHi; grow = bm + r; }
        else if (tile == 1) { base = aLo; grow = bm + r; }
        else if (tile == 2) { base = bHi; grow = bn + r; }
        else                { base = bLo; grow = bn + r; }
        const char* src = (const char*)(base + (size_t)grow * K + k0 + c * 8);
        uint32_t dst = st + tile * TILE_B + (r * ASTRIDE + c * 8) * 2;
        CP_ASYNC16(dst, src);
    }
}

__global__ __launch_bounds__(256, 1)
void gemm_mma(const __nv_bfloat16* __restrict__ aHi, const __nv_bfloat16* __restrict__ aLo,
              const __nv_bfloat16* __restrict__ bHi, const __nv_bfloat16* __restrict__ bLo,
              float* __restrict__ C, int K, int ldn, int mode, int pos0)
{
    extern __shared__ char smem[];
    const uint32_t sb = smem_u32(smem);
    const int tid = threadIdx.x;
    const int wid = tid >> 5;
    const int lane = tid & 31;
    const int bm = blockIdx.y * TM;
    const int bn = blockIdx.x * TN;
    const int wm = (wid >> 2) * 64;
    const int wn = (wid & 3) * 32;
    const int nch = K / TK;

    float acc[4][4][4];
#pragma unroll
    for (int mt = 0; mt < 4; mt++)
#pragma unroll
        for (int nt = 0; nt < 4; nt++)
#pragma unroll
            for (int i = 0; i < 4; i++) acc[mt][nt][i] = 0.0f;

    g_load_stage(sb, 0, tid, aHi, aLo, bHi, bLo, bm, bn, K, 0);
    CP_COMMIT();

    for (int c = 0; c < nch; c++) {
        if (c + 1 < nch)
            g_load_stage(sb, (c + 1) & 1, tid, aHi, aLo, bHi, bLo, bm, bn, K, (c + 1) * TK);
        CP_COMMIT();
        CP_WAIT1();
        __syncthreads();

        const uint32_t st = sb + (c & 1) * STG_B;
#pragma unroll
        for (int kg = 0; kg < 2; kg++) {
            uint32_t ah[4][4], al[4][4], bh[2][4], bl[2][4];
            const int acol = kg * 16 + (lane >> 4) * 8;
#pragma unroll
            for (int mt = 0; mt < 4; mt++) {
                int row = wm + mt * 16 + (lane & 15);
                uint32_t ad = st + (row * ASTRIDE + acol) * 2;
                LDSM_X4(ah[mt][0], ah[mt][1], ah[mt][2], ah[mt][3], ad);
                LDSM_X4(al[mt][0], al[mt][1], al[mt][2], al[mt][3], ad + OFF_ALO);
            }
            const int bcol = kg * 16 + ((lane >> 3) & 1) * 8;
#pragma unroll
            for (int p = 0; p < 2; p++) {
                int brow = wn + p * 16 + (lane & 7) + (lane >> 4) * 8;
                uint32_t bd = st + OFF_BHI + (brow * ASTRIDE + bcol) * 2;
                LDSM_X4(bh[p][0], bh[p][1], bh[p][2], bh[p][3], bd);
                LDSM_X4(bl[p][0], bl[p][1], bl[p][2], bl[p][3], bd + TILE_B);
            }
#pragma unroll
            for (int mt = 0; mt < 4; mt++)
#pragma unroll
                for (int nt = 0; nt < 4; nt++) {
                    const int p = nt >> 1, q = (nt & 1) * 2;
                    MMA16816(acc[mt][nt], ah[mt], &bh[p][q]);
                    MMA16816(acc[mt][nt], ah[mt], &bl[p][q]);
                    MMA16816(acc[mt][nt], al[mt], &bh[p][q]);
                }
        }
        __syncthreads();
    }

#pragma unroll
    for (int mt = 0; mt < 4; mt++)
#pragma unroll
        for (int nt = 0; nt < 4; nt++) {
            int row = bm + wm + mt * 16 + (lane >> 2);
            int col = bn + wn + nt * 8 + (lane & 3) * 2;
            float2 v0 = make_float2(acc[mt][nt][0], acc[mt][nt][1]);
            float2 v1 = make_float2(acc[mt][nt][2], acc[mt][nt][3]);
            if (mode == 0) {
                *(float2*)(C + (size_t)row * ldn + col) = v0;
                *(float2*)(C + (size_t)(row + 8) * ldn + col) = v1;
            } else {
                const int head = col >> 7;
                const int hd = col & 127;
                float* base = C + (size_t)head * KVSTRIDE + hd;
                *(float2*)(base + (size_t)(pos0 + row) * HD) = v0;
                *(float2*)(base + (size_t)(pos0 + row + 8) * HD) = v1;
            }
        }
}

// ---------------------------------------------------------------------------
// fp32 -> (bf16 hi, bf16 lo) split
// ---------------------------------------------------------------------------
__global__ void cvt_split(const float4* __restrict__ x,
                          __nv_bfloat162* __restrict__ hi,
                          __nv_bfloat162* __restrict__ lo, int n4)
{
    int i = blockIdx.x * blockDim.x + threadIdx.x;
    if (i >= n4) return;
    float4 v = x[i];
    __nv_bfloat16 hx = __float2bfloat16_rn(v.x);
    __nv_bfloat16 hy = __float2bfloat16_rn(v.y);
    __nv_bfloat16 hz = __float2bfloat16_rn(v.z);
    __nv_bfloat16 hw = __float2bfloat16_rn(v.w);
    __nv_bfloat16 lx = __float2bfloat16_rn(v.x - __bfloat162float(hx));
    __nv_bfloat16 ly = __float2bfloat16_rn(v.y - __bfloat162float(hy));
    __nv_bfloat16 lz = __float2bfloat16_rn(v.z - __bfloat162float(hz));
    __nv_bfloat16 lw = __float2bfloat16_rn(v.w - __bfloat162float(hw));
    hi[2 * i + 0] = __halves2bfloat162(hx, hy);
    hi[2 * i + 1] = __halves2bfloat162(hz, hw);
    lo[2 * i + 0] = __halves2bfloat162(lx, ly);
    lo[2 * i + 1] = __halves2bfloat162(lz, lw);
}

// ---------------------------------------------------------------------------
// RoPE -> bf16 hi/lo split outputs
// Q also folds in (1/sqrt(128))*log2(e) so attention can use exp2.
// ---------------------------------------------------------------------------
__global__ void rope_q_split(const float* __restrict__ Q,
                             const float* __restrict__ cosb,
                             const float* __restrict__ sinb,
                             __nv_bfloat16* __restrict__ qh,
                             __nv_bfloat16* __restrict__ ql)
{
    int idx = blockIdx.x * blockDim.x + threadIdx.x;   // QL*NH*64
    int hd = idx & 63;
    int t  = idx >> 6;
    int h  = t & (NH - 1);
    int s  = t >> 5;
    int pos = CTX + s;
    float c1 = cosb[(size_t)pos * HD + hd];
    float s1 = sinb[(size_t)pos * HD + hd];
    float c2 = cosb[(size_t)pos * HD + hd + 64];
    float s2 = sinb[(size_t)pos * HD + hd + 64];
    const float* p = Q + (size_t)s * HDIM + h * HD;
    float x1 = p[hd];
    float x2 = p[hd + 64];
    float y1 = (x1 * c1 - x2 * s1) * QSCALE;
    float y2 = (x2 * c2 + x1 * s2) * QSCALE;
    size_t o1 = (size_t)s * HDIM + h * HD + hd;
    __nv_bfloat16 h1 = __float2bfloat16_rn(y1);
    __nv_bfloat16 h2 = __float2bfloat16_rn(y2);
    qh[o1]      = h1;  ql[o1]      = __float2bfloat16_rn(y1 - __bfloat162float(h1));
    qh[o1 + 64] = h2;  ql[o1 + 64] = __float2bfloat16_rn(y2 - __bfloat162float(h2));
}

__global__ void rope_k_split(const float* __restrict__ Kb,
                             const float* __restrict__ cosb,
                             const float* __restrict__ sinb,
                             __nv_bfloat16* __restrict__ kh,
                             __nv_bfloat16* __restrict__ kl)
{
    int idx = blockIdx.x * blockDim.x + threadIdx.x;   // NKV*KVLEN*64
    int hd = idx & 63;
    int t  = idx >> 6;
    int pos = t & (KVLEN - 1);
    int kvh = t >> 12;
    float c1 = cosb[(size_t)pos * HD + hd];
    float s1 = sinb[(size_t)pos * HD + hd];
    float c2 = cosb[(size_t)pos * HD + hd + 64];
    float s2 = sinb[(size_t)pos * HD + hd + 64];
    const float* p = Kb + (size_t)kvh * KVSTRIDE + (size_t)pos * HD;
    float x1 = p[hd];
    float x2 = p[hd + 64];
    float y1 = x1 * c1 - x2 * s1;
    float y2 = x2 * c2 + x1 * s2;
    size_t o1 = (size_t)kvh * KVSTRIDE + (size_t)pos * HD + hd;
    __nv_bfloat16 h1 = __float2bfloat16_rn(y1);
    __nv_bfloat16 h2 = __float2bfloat16_rn(y2);
    kh[o1]      = h1;  kl[o1]      = __float2bfloat16_rn(y1 - __bfloat162float(h1));
    kh[o1 + 64] = h2;  kl[o1 + 64] = __float2bfloat16_rn(y2 - __bfloat162float(h2));
}

// ---------------------------------------------------------------------------
// Tensor-core flash attention (bf16 3-pass split, mma.sync).
// CTA = (q-tile 128, head); 8 warps x 16 rows. KV chunk 64, double-buffered.
// Writes O directly as bf16 hi/lo for the Wo projection.
// ---------------------------------------------------------------------------
#define BQ 128
#define BKV 64
#define RSTR 272                 // smem row stride bytes (136 bf16)
#define SQ_H 0
#define SQ_L 34816
#define SSTG 69632               // first stage offset
#define STG_SZ 69632
#define T_KH 0
#define T_KL 17408
#define T_VH 34816
#define T_VL 52224
#define ATTN_SMEM (SSTG + 2 * STG_SZ)   // 208896 bytes

__device__ __forceinline__ void attn_load_kv(
    uint32_t sb, int stage, int tid, int kvh, int kc)
{
    const uint32_t st = sb + SSTG + stage * STG_SZ;
    const size_t base = (size_t)kvh * KVSTRIDE + (size_t)kc * BKV * HD;
    const __nv_bfloat16* srcs[4] = { g_Kh + base, g_Kl + base, g_Vh + base, g_Vl + base };
#pragma unroll
    for (int t = 0; t < 16; t++) {
        int idx = tid + 256 * t;            // 0..4095
        int tile = idx >> 10;               // 0..3
        int rem = idx & 1023;
        int r = rem >> 4;                   // 0..63
        int c = rem & 15;                   // 16B chunk
        const char* src = (const char*)(srcs[tile] + (size_t)r * HD) + c * 16;
        uint32_t dst = st + tile * 17408 + r * RSTR + c * 16;
        CP_ASYNC16(dst, src);
    }
}

__global__ __launch_bounds__(256, 1)
void attn_mma(const __nv_bfloat16* __restrict__ Qh, const __nv_bfloat16* __restrict__ Ql,
              __nv_bfloat16* __restrict__ OHi, __nv_bfloat16* __restrict__ OLo)
{
    extern __shared__ char smem[];
    const uint32_t sb = smem_u32(smem);
    const int tid = threadIdx.x;
    const int wid = tid >> 5;
    const int lane = tid & 31;
    const int h  = blockIdx.y;
    const int q0 = blockIdx.x * BQ;
    const int kvh = h >> 2;

    // Load Q tile (hi+lo) into smem
#pragma unroll
    for (int t = 0; t < 16; t++) {
        int idx = tid + 256 * t;            // 0..4095
        int tile = idx >> 11;               // 0: hi, 1: lo
        int rem = idx & 2047;
        int r = rem >> 4;                   // 0..127
        int c = rem & 15;
        const __nv_bfloat16* base = tile ? Ql : Qh;
        const char* src = (const char*)(base + (size_t)(q0 + r) * HDIM + h * HD) + c * 16;
        uint32_t dst = sb + tile * 34816 + r * RSTR + c * 16;
        CP_ASYNC16(dst, src);
    }
    CP_COMMIT();
    attn_load_kv(sb, 0, tid, kvh, 0);
    CP_COMMIT();

    float o[16][4];
#pragma unroll
    for (int nt = 0; nt < 16; nt++)
#pragma unroll
        for (int i = 0; i < 4; i++) o[nt][i] = 0.0f;
    float m0 = -INFINITY, m1 = -INFINITY, l0 = 0.0f, l1 = 0.0f;

    const int NCH = KVLEN / BKV;            // 64
    for (int kc = 0; kc < NCH; kc++) {
        if (kc + 1 < NCH) attn_load_kv(sb, (kc + 1) & 1, tid, kvh, kc + 1);
        CP_COMMIT();
        CP_WAIT1();
        __syncthreads();

        const uint32_t st = sb + SSTG + (kc & 1) * STG_SZ;

        // ---- S = Q K^T (3-pass split) ----
        float s[8][4];
#pragma unroll
        for (int nt = 0; nt < 8; nt++)
#pragma unroll
            for (int i = 0; i < 4; i++) s[nt][i] = 0.0f;

#pragma unroll
        for (int d16 = 0; d16 < 8; d16++) {
            uint32_t qhf[4], qlf[4];
            const int arow = wid * 16 + (lane & 15);
            const int acol = d16 * 16 + (lane >> 4) * 8;
            uint32_t aaddr = sb + arow * RSTR + acol * 2;
            LDSM_X4(qhf[0], qhf[1], qhf[2], qhf[3], aaddr);
            LDSM_X4(qlf[0], qlf[1], qlf[2], qlf[3], aaddr + SQ_L);
            const int bcol = d16 * 16 + ((lane >> 3) & 1) * 8;
#pragma unroll
            for (int nt2 = 0; nt2 < 4; nt2++) {
                uint32_t bh[4], bl[4];
                const int brow = nt2 * 16 + (lane & 7) + (lane >> 4) * 8;
                uint32_t baddr = st + T_KH + brow * RSTR + bcol * 2;
                LDSM_X4(bh[0], bh[1], bh[2], bh[3], baddr);
                LDSM_X4(bl[0], bl[1], bl[2], bl[3], baddr + (T_KL - T_KH));
                MMA16816(s[2 * nt2],     qhf, &bh[0]);
                MMA16816(s[2 * nt2 + 1], qhf, &bh[2]);
                MMA16816(s[2 * nt2],     qhf, &bl[0]);
                MMA16816(s[2 * nt2 + 1], qhf, &bl[2]);
                MMA16816(s[2 * nt2],     qlf, &bh[0]);
                MMA16816(s[2 * nt2 + 1], qlf, &bh[2]);
            }
        }

        // ---- online softmax (rows: r=lane>>2 and r+8) ----
        float mloc0 = -INFINITY, mloc1 = -INFINITY;
#pragma unroll
        for (int nt = 0; nt < 8; nt++) {
            mloc0 = fmaxf(mloc0, fmaxf(s[nt][0], s[nt][1]));
            mloc1 = fmaxf(mloc1, fmaxf(s[nt][2], s[nt][3]));
        }
        mloc0 = fmaxf(mloc0, __shfl_xor_sync(0xffffffffu, mloc0, 1));
        mloc0 = fmaxf(mloc0, __shfl_xor_sync(0xffffffffu, mloc0, 2));
        mloc1 = fmaxf(mloc1, __shfl_xor_sync(0xffffffffu, mloc1, 1));
        mloc1 = fmaxf(mloc1, __shfl_xor_sync(0xffffffffu, mloc1, 2));
        float mn0 = fmaxf(m0, mloc0), mn1 = fmaxf(m1, mloc1);
        float a0 = exp2f(m0 - mn0), a1 = exp2f(m1 - mn1);
        m0 = mn0; m1 = mn1;

        float ll0 = 0.0f, ll1 = 0.0f;
        uint32_t ph[4][4], pl[4][4];
#pragma unroll
        for (int nt = 0; nt < 8; nt++) {
            float p0 = exp2f(s[nt][0] - mn0);
            float p1 = exp2f(s[nt][1] - mn0);
            float p2 = exp2f(s[nt][2] - mn1);
            float p3 = exp2f(s[nt][3] - mn1);
            ll0 += p0 + p1; ll1 += p2 + p3;
            uint32_t hA, hB;
            PACK_BF16X2(hA, p0, p1);
            PACK_BF16X2(hB, p2, p3);
            float r0 = p0 - __uint_as_float(hA << 16);
            float r1 = p1 - __uint_as_float(hA & 0xFFFF0000u);
            float r2 = p2 - __uint_as_float(hB << 16);
            float r3 = p3 - __uint_as_float(hB & 0xFFFF0000u);
            uint32_t lA, lB;
            PACK_BF16X2(lA, r0, r1);
            PACK_BF16X2(lB, r2, r3);
            const int kp = nt >> 1, hi8 = (nt & 1) * 2;
            ph[kp][hi8] = hA; ph[kp][hi8 + 1] = hB;
            pl[kp][hi8] = lA; pl[kp][hi8 + 1] = lB;
        }
        ll0 += __shfl_xor_sync(0xffffffffu, ll0, 1);
        ll0 += __shfl_xor_sync(0xffffffffu, ll0, 2);
        ll1 += __shfl_xor_sync(0xffffffffu, ll1, 1);
        ll1 += __shfl_xor_sync(0xffffffffu, ll1, 2);
        l0 = l0 * a0 + ll0;
        l1 = l1 * a1 + ll1;
#pragma unroll
        for (int nt = 0; nt < 16; nt++) {
            o[nt][0] *= a0; o[nt][1] *= a0;
            o[nt][2] *= a1; o[nt][3] *= a1;
        }

        // ---- O += P V (3-pass split), V via ldmatrix.trans ----
#pragma unroll
        for (int kp = 0; kp < 4; kp++) {
            const int vrow = kp * 16 + (lane & 7) + ((lane >> 3) & 1) * 8;
#pragma unroll
            for (int nt2 = 0; nt2 < 8; nt2++) {
                uint32_t vh[4], vl[4];
                const int vcol = nt2 * 16 + (lane >> 4) * 8;
                uint32_t vaddr = st + T_VH + vrow * RSTR + vcol * 2;
                LDSM_X4_T(vh[0], vh[1], vh[2], vh[3], vaddr);
                LDSM_X4_T(vl[0], vl[1], vl[2], vl[3], vaddr + (T_VL - T_VH));
                MMA16816(o[2 * nt2],     ph[kp], &vh[0]);
                MMA16816(o[2 * nt2 + 1], ph[kp], &vh[2]);
                MMA16816(o[2 * nt2],     ph[kp], &vl[0]);
                MMA16816(o[2 * nt2 + 1], ph[kp], &vl[2]);
                MMA16816(o[2 * nt2],     pl[kp], &vh[0]);
                MMA16816(o[2 * nt2 + 1], pl[kp], &vh[2]);
            }
        }
        __syncthreads();
    }

    // ---- epilogue: normalize, split to bf16 hi/lo, store ----
    const float inv0 = 1.0f / l0, inv1 = 1.0f / l1;
    const int row0 = q0 + wid * 16 + (lane >> 2);
#pragma unroll
    for (int nt = 0; nt < 16; nt++) {
        const int col = nt * 8 + (lane & 3) * 2;
        const size_t idx0 = ((size_t)row0 * HDIM + h * HD + col) >> 1;
        const size_t idx1 = ((size_t)(row0 + 8) * HDIM + h * HD + col) >> 1;
        float f0 = o[nt][0] * inv0, f1 = o[nt][1] * inv0;
        float f2 = o[nt][2] * inv1, f3 = o[nt][3] * inv1;
        uint32_t h0, h1, l0w, l1w;
        PACK_BF16X2(h0, f0, f1);
        PACK_BF16X2(h1, f2, f3);
        float r0 = f0 - __uint_as_float(h0 << 16);
        float r1 = f1 - __uint_as_float(h0 & 0xFFFF0000u);
        float r2 = f2 - __uint_as_float(h1 << 16);
        float r3 = f3 - __uint_as_float(h1 & 0xFFFF0000u);
        PACK_BF16X2(l0w, r0, r1);
        PACK_BF16X2(l1w, r2, r3);
        ((uint32_t*)OHi)[idx0] = h0;
        ((uint32_t*)OLo)[idx0] = l0w;
        ((uint32_t*)OHi)[idx1] = h1;
        ((uint32_t*)OLo)[idx1] = l1w;
    }
}

// ---------------------------------------------------------------------------
// Launch
// ---------------------------------------------------------------------------
extern "C" void kernel_launch(void* const* d_in, const int* in_sizes, int n_in,
                              void* d_out, int out_size)
{
    (void)in_sizes; (void)n_in; (void)out_size;
    const float* hidden = (const float*)d_in[0];
    const float* target = (const float*)d_in[1];
    const float* cosb   = (const float*)d_in[2];
    const float* sinb   = (const float*)d_in[3];
    float* out = (float*)d_out;

    float *Qp, *Kp, *Vp;
    cudaGetSymbolAddress((void**)&Qp, g_Q);
    cudaGetSymbolAddress((void**)&Kp, g_K);
    cudaGetSymbolAddress((void**)&Vp, g_V);

    __nv_bfloat16 *hidHi, *hidLo, *tgtHi, *tgtLo, *WqHi, *WqLo, *WkHi, *WkLo,
                  *WvHi, *WvLo, *WoHi, *WoLo, *AHi, *ALo,
                  *Qhp, *Qlp, *Khp, *Klp, *Vhp, *Vlp;
    cudaGetSymbolAddress((void**)&hidHi, g_hidHi);
    cudaGetSymbolAddress((void**)&hidLo, g_hidLo);
    cudaGetSymbolAddress((void**)&tgtHi, g_tgtHi);
    cudaGetSymbolAddress((void**)&tgtLo, g_tgtLo);
    cudaGetSymbolAddress((void**)&WqHi, g_WqHi);
    cudaGetSymbolAddress((void**)&WqLo, g_WqLo);
    cudaGetSymbolAddress((void**)&WkHi, g_WkHi);
    cudaGetSymbolAddress((void**)&WkLo, g_WkLo);
    cudaGetSymbolAddress((void**)&WvHi, g_WvHi);
    cudaGetSymbolAddress((void**)&WvLo, g_WvLo);
    cudaGetSymbolAddress((void**)&WoHi, g_WoHi);
    cudaGetSymbolAddress((void**)&WoLo, g_WoLo);
    cudaGetSymbolAddress((void**)&AHi, g_AHi);
    cudaGetSymbolAddress((void**)&ALo, g_ALo);
    cudaGetSymbolAddress((void**)&Qhp, g_Qh);
    cudaGetSymbolAddress((void**)&Qlp, g_Ql);
    cudaGetSymbolAddress((void**)&Khp, g_Kh);
    cudaGetSymbolAddress((void**)&Klp, g_Kl);
    cudaGetSymbolAddress((void**)&Vhp, g_Vh);
    cudaGetSymbolAddress((void**)&Vlp, g_Vl);

    cudaFuncSetAttribute(gemm_mma, cudaFuncAttributeMaxDynamicSharedMemorySize, SMEM_G);
    cudaFuncSetAttribute(attn_mma, cudaFuncAttributeMaxDynamicSharedMemorySize, ATTN_SMEM);

    // fp32 -> bf16 hi/lo splits of inputs/weights
    {
        int n;
        n = QL * HDIM;
        cvt_split<<<n / 4 / 256, 256>>>((const float4*)hidden, (__nv_bfloat162*)hidHi, (__nv_bfloat162*)hidLo, n / 4);
        n = CTX * HDIM;
        cvt_split<<<n / 4 / 256, 256>>>((const float4*)target, (__nv_bfloat162*)tgtHi, (__nv_bfloat162*)tgtLo, n / 4);
        n = HDIM * HDIM;
        cvt_split<<<n / 4 / 256, 256>>>((const float4*)d_in[4], (__nv_bfloat162*)WqHi, (__nv_bfloat162*)WqLo, n / 4);
        n = NKV * HD * HDIM;
        cvt_split<<<n / 4 / 256, 256>>>((const float4*)d_in[5], (__nv_bfloat162*)WkHi, (__nv_bfloat162*)WkLo, n / 4);
        cvt_split<<<n / 4 / 256, 256>>>((const float4*)d_in[6], (__nv_bfloat162*)WvHi, (__nv_bfloat162*)WvLo, n / 4);
        n = HDIM * HDIM;
        cvt_split<<<n / 4 / 256, 256>>>((const float4*)d_in[7], (__nv_bfloat162*)WoHi, (__nv_bfloat162*)WoLo, n / 4);
    }

    // Projections (HMMA, bf16 3-pass split)
    gemm_mma<<<dim3(HDIM / TN, QL / TM), 256, SMEM_G>>>(hidHi, hidLo, WqHi, WqLo, Qp, HDIM, HDIM, 0, 0);
    gemm_mma<<<dim3((NKV * HD) / TN, CTX / TM), 256, SMEM_G>>>(tgtHi, tgtLo, WkHi, WkLo, Kp, HDIM, 0, 1, 0);
    gemm_mma<<<dim3((NKV * HD) / TN, QL / TM), 256, SMEM_G>>>(hidHi, hidLo, WkHi, WkLo, Kp, HDIM, 0, 1, CTX);
    gemm_mma<<<dim3((NKV * HD) / TN, CTX / TM), 256, SMEM_G>>>(tgtHi, tgtLo, WvHi, WvLo, Vp, HDIM, 0, 1, 0);
    gemm_mma<<<dim3((NKV * HD) / TN, QL / TM), 256, SMEM_G>>>(hidHi, hidLo, WvHi, WvLo, Vp, HDIM, 0, 1, CTX);

    // RoPE + splits for attention operands
    rope_q_split<<<(QL * NH * 64) / 256, 256>>>(Qp, cosb, sinb, Qhp, Qlp);
    rope_k_split<<<(NKV * KVLEN * 64) / 256, 256>>>(Kp, cosb, sinb, Khp, Klp);
    {
        int n = NKV * KVLEN * HD;
        cvt_split<<<n / 4 / 256, 256>>>((const float4*)Vp, (__nv_bfloat162*)Vhp, (__nv_bfloat162*)Vlp, n / 4);
    }

    // Flash attention (HMMA, 3-pass split); writes bf16 hi/lo for Wo
    attn_mma<<<dim3(QL / BQ, NH), 256, ATTN_SMEM>>>(Qhp, Qlp, AHi, ALo);

    // Output projection
    gemm_mma<<<dim3(HDIM / TN, QL / TM), 256, SMEM_G>>>(AHi, ALo, WoHi, WoLo, out, HDIM, HDIM, 0, 0);
}

// round 7
// speedup vs baseline: 3.3536x; 1.0727x over previous
#include <cuda_runtime.h>
#include <cuda_bf16.h>
#include <math.h>
#include <stdint.h>

// Problem dims
#define QL 2048
#define CTX 2048
#define HDIM 4096
#define NH 32
#define NKV 8
#define HD 128
#define KVLEN (CTX + QL)          // 4096
#define KVSTRIDE (KVLEN * HD)     // elements per kv head

#define QSCALE (0.08838834764831845f * 1.4426950408889634f)   // (1/sqrt(128))*log2(e)

// ---------------------------------------------------------------------------
// Scratch (__device__ globals; allocation-free rule)
// ---------------------------------------------------------------------------
__device__ float g_Q[(size_t)QL * HDIM];
__device__ float g_K[(size_t)NKV * KVLEN * HD];
__device__ float g_V[(size_t)NKV * KVLEN * HD];

__device__ __nv_bfloat16 g_hidHi[(size_t)QL * HDIM],  g_hidLo[(size_t)QL * HDIM];
__device__ __nv_bfloat16 g_tgtHi[(size_t)CTX * HDIM], g_tgtLo[(size_t)CTX * HDIM];
__device__ __nv_bfloat16 g_WqHi[(size_t)HDIM * HDIM], g_WqLo[(size_t)HDIM * HDIM];
__device__ __nv_bfloat16 g_WkHi[(size_t)NKV * HD * HDIM], g_WkLo[(size_t)NKV * HD * HDIM];
__device__ __nv_bfloat16 g_WvHi[(size_t)NKV * HD * HDIM], g_WvLo[(size_t)NKV * HD * HDIM];
__device__ __nv_bfloat16 g_WoHi[(size_t)HDIM * HDIM], g_WoLo[(size_t)HDIM * HDIM];
__device__ __nv_bfloat16 g_AHi[(size_t)QL * HDIM],  g_ALo[(size_t)QL * HDIM];

__device__ __nv_bfloat16 g_Qh[(size_t)QL * HDIM],  g_Ql[(size_t)QL * HDIM];
__device__ __nv_bfloat16 g_Kh[(size_t)NKV * KVLEN * HD], g_Kl[(size_t)NKV * KVLEN * HD];
__device__ __nv_bfloat16 g_Vh[(size_t)NKV * KVLEN * HD], g_Vl[(size_t)NKV * KVLEN * HD];

// ---------------------------------------------------------------------------
// PTX helpers (base sm_103-legal only: cp.async, ldmatrix, mma.sync)
// ---------------------------------------------------------------------------
__device__ __forceinline__ uint32_t smem_u32(const void* p) {
    uint32_t a;
    asm("{ .reg .u64 t; cvta.to.shared.u64 t, %1; cvt.u32.u64 %0, t; }" : "=r"(a) : "l"(p));
    return a;
}
#define CP_ASYNC16(dst, src) \
    asm volatile("cp.async.cg.shared.global [%0], [%1], 16;" :: "r"(dst), "l"(src))
#define CP_COMMIT() asm volatile("cp.async.commit_group;" ::: "memory")
#define CP_WAIT1()  asm volatile("cp.async.wait_group 1;" ::: "memory")

#define LDSM_X4(r0, r1, r2, r3, addr) \
    asm volatile("ldmatrix.sync.aligned.m8n8.x4.shared.b16 {%0,%1,%2,%3}, [%4];" \
                 : "=r"(r0), "=r"(r1), "=r"(r2), "=r"(r3) : "r"(addr))
#define LDSM_X4_T(r0, r1, r2, r3, addr) \
    asm volatile("ldmatrix.sync.aligned.m8n8.x4.trans.shared.b16 {%0,%1,%2,%3}, [%4];" \
                 : "=r"(r0), "=r"(r1), "=r"(r2), "=r"(r3) : "r"(addr))

#define MMA16816(d, a, b) \
    asm volatile("mma.sync.aligned.m16n8k16.row.col.f32.bf16.bf16.f32 " \
                 "{%0,%1,%2,%3}, {%4,%5,%6,%7}, {%8,%9}, {%0,%1,%2,%3};" \
                 : "+f"((d)[0]), "+f"((d)[1]), "+f"((d)[2]), "+f"((d)[3]) \
                 : "r"((a)[0]), "r"((a)[1]), "r"((a)[2]), "r"((a)[3]), \
                   "r"((b)[0]), "r"((b)[1]))

#define PACK_BF16X2(r, flo, fhi) \
    asm("cvt.rn.bf16x2.f32 %0, %1, %2;" : "=r"(r) : "f"(fhi), "f"(flo))

// ---------------------------------------------------------------------------
// bf16-split HMMA GEMM v2: C[M,N] = A[M,K] * W[N,K]^T
// Tile 128x256, K-chunk 32, 3-stage cp.async pipeline, 256 threads.
// Warp (wid): rows (wid>>2)*64, cols (wid&3)*64; 4x8 m16n8 tiles per warp.
// mode 0: C row-major [., ldn];  mode 1: KV layout C[head][pos0+row][hd].
// ---------------------------------------------------------------------------
#define TM 128
#define TN 256
#define TK 32
#define ASTRIDE 40                        // bf16 per smem row (32 data + 8 pad)
#define A_TILE_B (128 * ASTRIDE * 2)      // 10240
#define B_TILE_B (256 * ASTRIDE * 2)      // 20480
#define OFF_ALO A_TILE_B                  // 10240
#define OFF_BHI (2 * A_TILE_B)            // 20480
#define OFF_BLO (2 * A_TILE_B + B_TILE_B) // 40960
#define STG_B (2 * A_TILE_B + 2 * B_TILE_B)   // 61440
#define SMEM_G (3 * STG_B)                // 184320

__device__ __forceinline__ void g_load_stage(
    uint32_t sb, int stage, int tid,
    const __nv_bfloat16* aHi, const __nv_bfloat16* aLo,
    const __nv_bfloat16* bHi, const __nv_bfloat16* bLo,
    int bm, int bn, int K, int k0)
{
    const uint32_t st = sb + stage * STG_B;
#pragma unroll
    for (int t = 0; t < 12; t++) {
        int idx = tid + 256 * t;          // 0..3071
        const __nv_bfloat16* base;
        int grow, r;
        uint32_t toff;
        if (idx < 512)       { base = aHi; r = idx >> 2;           grow = bm + r; toff = 0; }
        else if (idx < 1024) { base = aLo; r = (idx - 512) >> 2;   grow = bm + r; toff = OFF_ALO; }
        else if (idx < 2048) { base = bHi; r = (idx - 1024) >> 2;  grow = bn + r; toff = OFF_BHI; }
        else                 { base = bLo; r = (idx - 2048) >> 2;  grow = bn + r; toff = OFF_BLO; }
        int c = idx & 3;
        const char* src = (const char*)(base + (size_t)grow * K + k0 + c * 8);
        uint32_t dst = st + toff + r * 80 + c * 16;
        CP_ASYNC16(dst, src);
    }
}

__global__ __launch_bounds__(256, 1)
void gemm_mma(const __nv_bfloat16* __restrict__ aHi, const __nv_bfloat16* __restrict__ aLo,
              const __nv_bfloat16* __restrict__ bHi, const __nv_bfloat16* __restrict__ bLo,
              float* __restrict__ C, int K, int ldn, int mode, int pos0)
{
    extern __shared__ char smem[];
    const uint32_t sb = smem_u32(smem);
    const int tid = threadIdx.x;
    const int wid = tid >> 5;
    const int lane = tid & 31;
    const int bm = blockIdx.y * TM;
    const int bn = blockIdx.x * TN;
    const int wm = (wid >> 2) * 64;
    const int wn = (wid & 3) * 64;
    const int nch = K / TK;

    float acc[4][8][4];
#pragma unroll
    for (int mt = 0; mt < 4; mt++)
#pragma unroll
        for (int nt = 0; nt < 8; nt++)
#pragma unroll
            for (int i = 0; i < 4; i++) acc[mt][nt][i] = 0.0f;

    g_load_stage(sb, 0, tid, aHi, aLo, bHi, bLo, bm, bn, K, 0);
    CP_COMMIT();
    g_load_stage(sb, 1, tid, aHi, aLo, bHi, bLo, bm, bn, K, TK);
    CP_COMMIT();

    int stage = 0;
    for (int c = 0; c < nch; c++) {
        CP_WAIT1();
        __syncthreads();
        if (c + 2 < nch) {
            int s2 = stage + 2; if (s2 >= 3) s2 -= 3;
            g_load_stage(sb, s2, tid, aHi, aLo, bHi, bLo, bm, bn, K, (c + 2) * TK);
        }
        CP_COMMIT();

        const uint32_t st = sb + stage * STG_B;
#pragma unroll
        for (int kg = 0; kg < 2; kg++) {
            uint32_t ah[4][4], al[4][4];
            const int acol = kg * 16 + (lane >> 4) * 8;
#pragma unroll
            for (int mt = 0; mt < 4; mt++) {
                int row = wm + mt * 16 + (lane & 15);
                uint32_t ad = st + row * 80 + acol * 2;
                LDSM_X4(ah[mt][0], ah[mt][1], ah[mt][2], ah[mt][3], ad);
                LDSM_X4(al[mt][0], al[mt][1], al[mt][2], al[mt][3], ad + OFF_ALO);
            }
            const int bcol = kg * 16 + ((lane >> 3) & 1) * 8;
#pragma unroll
            for (int p = 0; p < 4; p++) {
                uint32_t bh[4], bl[4];
                const int brow = wn + p * 16 + (lane & 7) + (lane >> 4) * 8;
                uint32_t bd = st + OFF_BHI + brow * 80 + bcol * 2;
                LDSM_X4(bh[0], bh[1], bh[2], bh[3], bd);
                LDSM_X4(bl[0], bl[1], bl[2], bl[3], bd + (OFF_BLO - OFF_BHI));
#pragma unroll
                for (int mt = 0; mt < 4; mt++) {
                    MMA16816(acc[mt][2 * p],     ah[mt], &bh[0]);
                    MMA16816(acc[mt][2 * p + 1], ah[mt], &bh[2]);
                    MMA16816(acc[mt][2 * p],     ah[mt], &bl[0]);
                    MMA16816(acc[mt][2 * p + 1], ah[mt], &bl[2]);
                    MMA16816(acc[mt][2 * p],     al[mt], &bh[0]);
                    MMA16816(acc[mt][2 * p + 1], al[mt], &bh[2]);
                }
            }
        }
        stage++; if (stage >= 3) stage = 0;
        __syncthreads();
    }

#pragma unroll
    for (int mt = 0; mt < 4; mt++)
#pragma unroll
        for (int nt = 0; nt < 8; nt++) {
            int row = bm + wm + mt * 16 + (lane >> 2);
            int col = bn + wn + nt * 8 + (lane & 3) * 2;
            float2 v0 = make_float2(acc[mt][nt][0], acc[mt][nt][1]);
            float2 v1 = make_float2(acc[mt][nt][2], acc[mt][nt][3]);
            if (mode == 0) {
                *(float2*)(C + (size_t)row * ldn + col) = v0;
                *(float2*)(C + (size_t)(row + 8) * ldn + col) = v1;
            } else {
                const int head = col >> 7;
                const int hd = col & 127;
                float* base = C + (size_t)head * KVSTRIDE + hd;
                *(float2*)(base + (size_t)(pos0 + row) * HD) = v0;
                *(float2*)(base + (size_t)(pos0 + row + 8) * HD) = v1;
            }
        }
}

// Fused KV projections: z selects (activation, weight, dest, pos0)
__global__ __launch_bounds__(256, 1)
void gemm_kv(float* __restrict__ Ko, float* __restrict__ Vo)
{
    const int z = blockIdx.z;
    const __nv_bfloat16 *aHi, *aLo, *bHi, *bLo;
    float* C;
    int pos0;
    if (z >> 1) { aHi = g_hidHi; aLo = g_hidLo; pos0 = CTX; }
    else        { aHi = g_tgtHi; aLo = g_tgtLo; pos0 = 0; }
    if (z & 1)  { bHi = g_WvHi; bLo = g_WvLo; C = Vo; }
    else        { bHi = g_WkHi; bLo = g_WkLo; C = Ko; }

    // inline call of the same body via function pointer not possible; replicate via
    // a device function would duplicate regs — simplest: call gemm core logic here.
    // We re-dispatch by computing on the same grid shape as gemm_mma mode 1.
    extern __shared__ char smem[];
    const uint32_t sb = smem_u32(smem);
    const int tid = threadIdx.x;
    const int wid = tid >> 5;
    const int lane = tid & 31;
    const int bm = blockIdx.y * TM;
    const int bn = blockIdx.x * TN;
    const int wm = (wid >> 2) * 64;
    const int wn = (wid & 3) * 64;
    const int K = HDIM;
    const int nch = K / TK;

    float acc[4][8][4];
#pragma unroll
    for (int mt = 0; mt < 4; mt++)
#pragma unroll
        for (int nt = 0; nt < 8; nt++)
#pragma unroll
            for (int i = 0; i < 4; i++) acc[mt][nt][i] = 0.0f;

    g_load_stage(sb, 0, tid, aHi, aLo, bHi, bLo, bm, bn, K, 0);
    CP_COMMIT();
    g_load_stage(sb, 1, tid, aHi, aLo, bHi, bLo, bm, bn, K, TK);
    CP_COMMIT();

    int stage = 0;
    for (int c = 0; c < nch; c++) {
        CP_WAIT1();
        __syncthreads();
        if (c + 2 < nch) {
            int s2 = stage + 2; if (s2 >= 3) s2 -= 3;
            g_load_stage(sb, s2, tid, aHi, aLo, bHi, bLo, bm, bn, K, (c + 2) * TK);
        }
        CP_COMMIT();

        const uint32_t st = sb + stage * STG_B;
#pragma unroll
        for (int kg = 0; kg < 2; kg++) {
            uint32_t ah[4][4], al[4][4];
            const int acol = kg * 16 + (lane >> 4) * 8;
#pragma unroll
            for (int mt = 0; mt < 4; mt++) {
                int row = wm + mt * 16 + (lane & 15);
                uint32_t ad = st + row * 80 + acol * 2;
                LDSM_X4(ah[mt][0], ah[mt][1], ah[mt][2], ah[mt][3], ad);
                LDSM_X4(al[mt][0], al[mt][1], al[mt][2], al[mt][3], ad + OFF_ALO);
            }
            const int bcol = kg * 16 + ((lane >> 3) & 1) * 8;
#pragma unroll
            for (int p = 0; p < 4; p++) {
                uint32_t bh[4], bl[4];
                const int brow = wn + p * 16 + (lane & 7) + (lane >> 4) * 8;
                uint32_t bd = st + OFF_BHI + brow * 80 + bcol * 2;
                LDSM_X4(bh[0], bh[1], bh[2], bh[3], bd);
                LDSM_X4(bl[0], bl[1], bl[2], bl[3], bd + (OFF_BLO - OFF_BHI));
#pragma unroll
                for (int mt = 0; mt < 4; mt++) {
                    MMA16816(acc[mt][2 * p],     ah[mt], &bh[0]);
                    MMA16816(acc[mt][2 * p + 1], ah[mt], &bh[2]);
                    MMA16816(acc[mt][2 * p],     ah[mt], &bl[0]);
                    MMA16816(acc[mt][2 * p + 1], ah[mt], &bl[2]);
                    MMA16816(acc[mt][2 * p],     al[mt], &bh[0]);
                    MMA16816(acc[mt][2 * p + 1], al[mt], &bh[2]);
                }
            }
        }
        stage++; if (stage >= 3) stage = 0;
        __syncthreads();
    }

#pragma unroll
    for (int mt = 0; mt < 4; mt++)
#pragma unroll
        for (int nt = 0; nt < 8; nt++) {
            int row = bm + wm + mt * 16 + (lane >> 2);
            int col = bn + wn + nt * 8 + (lane & 3) * 2;
            const int head = col >> 7;
            const int hd = col & 127;
            float* base = C + (size_t)head * KVSTRIDE + hd;
            *(float2*)(base + (size_t)(pos0 + row) * HD) =
                make_float2(acc[mt][nt][0], acc[mt][nt][1]);
            *(float2*)(base + (size_t)(pos0 + row + 8) * HD) =
                make_float2(acc[mt][nt][2], acc[mt][nt][3]);
        }
}

// ---------------------------------------------------------------------------
// fp32 -> (bf16 hi, bf16 lo) split
// ---------------------------------------------------------------------------
__global__ void cvt_split(const float4* __restrict__ x,
                          __nv_bfloat162* __restrict__ hi,
                          __nv_bfloat162* __restrict__ lo, int n4)
{
    int i = blockIdx.x * blockDim.x + threadIdx.x;
    if (i >= n4) return;
    float4 v = x[i];
    __nv_bfloat16 hx = __float2bfloat16_rn(v.x);
    __nv_bfloat16 hy = __float2bfloat16_rn(v.y);
    __nv_bfloat16 hz = __float2bfloat16_rn(v.z);
    __nv_bfloat16 hw = __float2bfloat16_rn(v.w);
    __nv_bfloat16 lx = __float2bfloat16_rn(v.x - __bfloat162float(hx));
    __nv_bfloat16 ly = __float2bfloat16_rn(v.y - __bfloat162float(hy));
    __nv_bfloat16 lz = __float2bfloat16_rn(v.z - __bfloat162float(hz));
    __nv_bfloat16 lw = __float2bfloat16_rn(v.w - __bfloat162float(hw));
    hi[2 * i + 0] = __halves2bfloat162(hx, hy);
    hi[2 * i + 1] = __halves2bfloat162(hz, hw);
    lo[2 * i + 0] = __halves2bfloat162(lx, ly);
    lo[2 * i + 1] = __halves2bfloat162(lz, lw);
}

// ---------------------------------------------------------------------------
// RoPE -> bf16 hi/lo split outputs (Q folds in scale*log2e)
// ---------------------------------------------------------------------------
__global__ void rope_q_split(const float* __restrict__ Q,
                             const float* __restrict__ cosb,
                             const float* __restrict__ sinb,
                             __nv_bfloat16* __restrict__ qh,
                             __nv_bfloat16* __restrict__ ql)
{
    int idx = blockIdx.x * blockDim.x + threadIdx.x;
    int hd = idx & 63;
    int t  = idx >> 6;
    int h  = t & (NH - 1);
    int s  = t >> 5;
    int pos = CTX + s;
    float c1 = cosb[(size_t)pos * HD + hd];
    float s1 = sinb[(size_t)pos * HD + hd];
    float c2 = cosb[(size_t)pos * HD + hd + 64];
    float s2 = sinb[(size_t)pos * HD + hd + 64];
    const float* p = Q + (size_t)s * HDIM + h * HD;
    float x1 = p[hd];
    float x2 = p[hd + 64];
    float y1 = (x1 * c1 - x2 * s1) * QSCALE;
    float y2 = (x2 * c2 + x1 * s2) * QSCALE;
    size_t o1 = (size_t)s * HDIM + h * HD + hd;
    __nv_bfloat16 h1 = __float2bfloat16_rn(y1);
    __nv_bfloat16 h2 = __float2bfloat16_rn(y2);
    qh[o1]      = h1;  ql[o1]      = __float2bfloat16_rn(y1 - __bfloat162float(h1));
    qh[o1 + 64] = h2;  ql[o1 + 64] = __float2bfloat16_rn(y2 - __bfloat162float(h2));
}

__global__ void rope_k_split(const float* __restrict__ Kb,
                             const float* __restrict__ cosb,
                             const float* __restrict__ sinb,
                             __nv_bfloat16* __restrict__ kh,
                             __nv_bfloat16* __restrict__ kl)
{
    int idx = blockIdx.x * blockDim.x + threadIdx.x;
    int hd = idx & 63;
    int t  = idx >> 6;
    int pos = t & (KVLEN - 1);
    int kvh = t >> 12;
    float c1 = cosb[(size_t)pos * HD + hd];
    float s1 = sinb[(size_t)pos * HD + hd];
    float c2 = cosb[(size_t)pos * HD + hd + 64];
    float s2 = sinb[(size_t)pos * HD + hd + 64];
    const float* p = Kb + (size_t)kvh * KVSTRIDE + (size_t)pos * HD;
    float x1 = p[hd];
    float x2 = p[hd + 64];
    float y1 = x1 * c1 - x2 * s1;
    float y2 = x2 * c2 + x1 * s2;
    size_t o1 = (size_t)kvh * KVSTRIDE + (size_t)pos * HD + hd;
    __nv_bfloat16 h1 = __float2bfloat16_rn(y1);
    __nv_bfloat16 h2 = __float2bfloat16_rn(y2);
    kh[o1]      = h1;  kl[o1]      = __float2bfloat16_rn(y1 - __bfloat162float(h1));
    kh[o1 + 64] = h2;  kl[o1 + 64] = __float2bfloat16_rn(y2 - __bfloat162float(h2));
}

// ---------------------------------------------------------------------------
// Tensor-core flash attention (bf16 3-pass split, mma.sync) — passing R5 version
// ---------------------------------------------------------------------------
#define BQ 128
#define BKV 64
#define RSTR 272
#define SQ_L 34816
#define SSTG 69632
#define STG_SZ 69632
#define T_KH 0
#define T_KL 17408
#define T_VH 34816
#define T_VL 52224
#define ATTN_SMEM (SSTG + 2 * STG_SZ)

__device__ __forceinline__ void attn_load_kv(
    uint32_t sb, int stage, int tid, int kvh, int kc)
{
    const uint32_t st = sb + SSTG + stage * STG_SZ;
    const size_t base = (size_t)kvh * KVSTRIDE + (size_t)kc * BKV * HD;
    const __nv_bfloat16* srcs[4] = { g_Kh + base, g_Kl + base, g_Vh + base, g_Vl + base };
#pragma unroll
    for (int t = 0; t < 16; t++) {
        int idx = tid + 256 * t;
        int tile = idx >> 10;
        int rem = idx & 1023;
        int r = rem >> 4;
        int c = rem & 15;
        const char* src = (const char*)(srcs[tile] + (size_t)r * HD) + c * 16;
        uint32_t dst = st + tile * 17408 + r * RSTR + c * 16;
        CP_ASYNC16(dst, src);
    }
}

__global__ __launch_bounds__(256, 1)
void attn_mma(const __nv_bfloat16* __restrict__ Qh, const __nv_bfloat16* __restrict__ Ql,
              __nv_bfloat16* __restrict__ OHi, __nv_bfloat16* __restrict__ OLo)
{
    extern __shared__ char smem[];
    const uint32_t sb = smem_u32(smem);
    const int tid = threadIdx.x;
    const int wid = tid >> 5;
    const int lane = tid & 31;
    const int h  = blockIdx.y;
    const int q0 = blockIdx.x * BQ;
    const int kvh = h >> 2;

#pragma unroll
    for (int t = 0; t < 16; t++) {
        int idx = tid + 256 * t;
        int tile = idx >> 11;
        int rem = idx & 2047;
        int r = rem >> 4;
        int c = rem & 15;
        const __nv_bfloat16* base = tile ? Ql : Qh;
        const char* src = (const char*)(base + (size_t)(q0 + r) * HDIM + h * HD) + c * 16;
        uint32_t dst = sb + tile * 34816 + r * RSTR + c * 16;
        CP_ASYNC16(dst, src);
    }
    CP_COMMIT();
    attn_load_kv(sb, 0, tid, kvh, 0);
    CP_COMMIT();

    float o[16][4];
#pragma unroll
    for (int nt = 0; nt < 16; nt++)
#pragma unroll
        for (int i = 0; i < 4; i++) o[nt][i] = 0.0f;
    float m0 = -INFINITY, m1 = -INFINITY, l0 = 0.0f, l1 = 0.0f;

    const int NCH = KVLEN / BKV;
    for (int kc = 0; kc < NCH; kc++) {
        if (kc + 1 < NCH) attn_load_kv(sb, (kc + 1) & 1, tid, kvh, kc + 1);
        CP_COMMIT();
        CP_WAIT1();
        __syncthreads();

        const uint32_t st = sb + SSTG + (kc & 1) * STG_SZ;

        float s[8][4];
#pragma unroll
        for (int nt = 0; nt < 8; nt++)
#pragma unroll
            for (int i = 0; i < 4; i++) s[nt][i] = 0.0f;

#pragma unroll
        for (int d16 = 0; d16 < 8; d16++) {
            uint32_t qhf[4], qlf[4];
            const int arow = wid * 16 + (lane & 15);
            const int acol = d16 * 16 + (lane >> 4) * 8;
            uint32_t aaddr = sb + arow * RSTR + acol * 2;
            LDSM_X4(qhf[0], qhf[1], qhf[2], qhf[3], aaddr);
            LDSM_X4(qlf[0], qlf[1], qlf[2], qlf[3], aaddr + SQ_L);
            const int bcol = d16 * 16 + ((lane >> 3) & 1) * 8;
#pragma unroll
            for (int nt2 = 0; nt2 < 4; nt2++) {
                uint32_t bh[4], bl[4];
                const int brow = nt2 * 16 + (lane & 7) + (lane >> 4) * 8;
                uint32_t baddr = st + T_KH + brow * RSTR + bcol * 2;
                LDSM_X4(bh[0], bh[1], bh[2], bh[3], baddr);
                LDSM_X4(bl[0], bl[1], bl[2], bl[3], baddr + (T_KL - T_KH));
                MMA16816(s[2 * nt2],     qhf, &bh[0]);
                MMA16816(s[2 * nt2 + 1], qhf, &bh[2]);
                MMA16816(s[2 * nt2],     qhf, &bl[0]);
                MMA16816(s[2 * nt2 + 1], qhf, &bl[2]);
                MMA16816(s[2 * nt2],     qlf, &bh[0]);
                MMA16816(s[2 * nt2 + 1], qlf, &bh[2]);
            }
        }

        float mloc0 = -INFINITY, mloc1 = -INFINITY;
#pragma unroll
        for (int nt = 0; nt < 8; nt++) {
            mloc0 = fmaxf(mloc0, fmaxf(s[nt][0], s[nt][1]));
            mloc1 = fmaxf(mloc1, fmaxf(s[nt][2], s[nt][3]));
        }
        mloc0 = fmaxf(mloc0, __shfl_xor_sync(0xffffffffu, mloc0, 1));
        mloc0 = fmaxf(mloc0, __shfl_xor_sync(0xffffffffu, mloc0, 2));
        mloc1 = fmaxf(mloc1, __shfl_xor_sync(0xffffffffu, mloc1, 1));
        mloc1 = fmaxf(mloc1, __shfl_xor_sync(0xffffffffu, mloc1, 2));
        float mn0 = fmaxf(m0, mloc0), mn1 = fmaxf(m1, mloc1);
        float a0 = exp2f(m0 - mn0), a1 = exp2f(m1 - mn1);
        m0 = mn0; m1 = mn1;

        float ll0 = 0.0f, ll1 = 0.0f;
        uint32_t ph[4][4], pl[4][4];
#pragma unroll
        for (int nt = 0; nt < 8; nt++) {
            float p0 = exp2f(s[nt][0] - mn0);
            float p1 = exp2f(s[nt][1] - mn0);
            float p2 = exp2f(s[nt][2] - mn1);
            float p3 = exp2f(s[nt][3] - mn1);
            ll0 += p0 + p1; ll1 += p2 + p3;
            uint32_t hA, hB;
            PACK_BF16X2(hA, p0, p1);
            PACK_BF16X2(hB, p2, p3);
            float r0 = p0 - __uint_as_float(hA << 16);
            float r1 = p1 - __uint_as_float(hA & 0xFFFF0000u);
            float r2 = p2 - __uint_as_float(hB << 16);
            float r3 = p3 - __uint_as_float(hB & 0xFFFF0000u);
            uint32_t lA, lB;
            PACK_BF16X2(lA, r0, r1);
            PACK_BF16X2(lB, r2, r3);
            const int kp = nt >> 1, hi8 = (nt & 1) * 2;
            ph[kp][hi8] = hA; ph[kp][hi8 + 1] = hB;
            pl[kp][hi8] = lA; pl[kp][hi8 + 1] = lB;
        }
        ll0 += __shfl_xor_sync(0xffffffffu, ll0, 1);
        ll0 += __shfl_xor_sync(0xffffffffu, ll0, 2);
        ll1 += __shfl_xor_sync(0xffffffffu, ll1, 1);
        ll1 += __shfl_xor_sync(0xffffffffu, ll1, 2);
        l0 = l0 * a0 + ll0;
        l1 = l1 * a1 + ll1;
#pragma unroll
        for (int nt = 0; nt < 16; nt++) {
            o[nt][0] *= a0; o[nt][1] *= a0;
            o[nt][2] *= a1; o[nt][3] *= a1;
        }

#pragma unroll
        for (int kp = 0; kp < 4; kp++) {
            const int vrow = kp * 16 + (lane & 7) + ((lane >> 3) & 1) * 8;
#pragma unroll
            for (int nt2 = 0; nt2 < 8; nt2++) {
                uint32_t vh[4], vl[4];
                const int vcol = nt2 * 16 + (lane >> 4) * 8;
                uint32_t vaddr = st + T_VH + vrow * RSTR + vcol * 2;
                LDSM_X4_T(vh[0], vh[1], vh[2], vh[3], vaddr);
                LDSM_X4_T(vl[0], vl[1], vl[2], vl[3], vaddr + (T_VL - T_VH));
                MMA16816(o[2 * nt2],     ph[kp], &vh[0]);
                MMA16816(o[2 * nt2 + 1], ph[kp], &vh[2]);
                MMA16816(o[2 * nt2],     ph[kp], &vl[0]);
                MMA16816(o[2 * nt2 + 1], ph[kp], &vl[2]);
                MMA16816(o[2 * nt2],     pl[kp], &vh[0]);
                MMA16816(o[2 * nt2 + 1], pl[kp], &vh[2]);
            }
        }
        __syncthreads();
    }

    const float inv0 = 1.0f / l0, inv1 = 1.0f / l1;
    const int row0 = q0 + wid * 16 + (lane >> 2);
#pragma unroll
    for (int nt = 0; nt < 16; nt++) {
        const int col = nt * 8 + (lane & 3) * 2;
        const size_t idx0 = ((size_t)row0 * HDIM + h * HD + col) >> 1;
        const size_t idx1 = ((size_t)(row0 + 8) * HDIM + h * HD + col) >> 1;
        float f0 = o[nt][0] * inv0, f1 = o[nt][1] * inv0;
        float f2 = o[nt][2] * inv1, f3 = o[nt][3] * inv1;
        uint32_t h0, h1, l0w, l1w;
        PACK_BF16X2(h0, f0, f1);
        PACK_BF16X2(h1, f2, f3);
        float r0 = f0 - __uint_as_float(h0 << 16);
        float r1 = f1 - __uint_as_float(h0 & 0xFFFF0000u);
        float r2 = f2 - __uint_as_float(h1 << 16);
        float r3 = f3 - __uint_as_float(h1 & 0xFFFF0000u);
        PACK_BF16X2(l0w, r0, r1);
        PACK_BF16X2(l1w, r2, r3);
        ((uint32_t*)OHi)[idx0] = h0;
        ((uint32_t*)OLo)[idx0] = l0w;
        ((uint32_t*)OHi)[idx1] = h1;
        ((uint32_t*)OLo)[idx1] = l1w;
    }
}

// ---------------------------------------------------------------------------
// Launch
// ---------------------------------------------------------------------------
extern "C" void kernel_launch(void* const* d_in, const int* in_sizes, int n_in,
                              void* d_out, int out_size)
{
    (void)in_sizes; (void)n_in; (void)out_size;
    const float* hidden = (const float*)d_in[0];
    const float* target = (const float*)d_in[1];
    const float* cosb   = (const float*)d_in[2];
    const float* sinb   = (const float*)d_in[3];
    float* out = (float*)d_out;

    float *Qp, *Kp, *Vp;
    cudaGetSymbolAddress((void**)&Qp, g_Q);
    cudaGetSymbolAddress((void**)&Kp, g_K);
    cudaGetSymbolAddress((void**)&Vp, g_V);

    __nv_bfloat16 *hidHi, *hidLo, *tgtHi, *tgtLo, *WqHi, *WqLo, *WkHi, *WkLo,
                  *WvHi, *WvLo, *WoHi, *WoLo, *AHi, *ALo,
                  *Qhp, *Qlp, *Khp, *Klp, *Vhp, *Vlp;
    cudaGetSymbolAddress((void**)&hidHi, g_hidHi);
    cudaGetSymbolAddress((void**)&hidLo, g_hidLo);
    cudaGetSymbolAddress((void**)&tgtHi, g_tgtHi);
    cudaGetSymbolAddress((void**)&tgtLo, g_tgtLo);
    cudaGetSymbolAddress((void**)&WqHi, g_WqHi);
    cudaGetSymbolAddress((void**)&WqLo, g_WqLo);
    cudaGetSymbolAddress((void**)&WkHi, g_WkHi);
    cudaGetSymbolAddress((void**)&WkLo, g_WkLo);
    cudaGetSymbolAddress((void**)&WvHi, g_WvHi);
    cudaGetSymbolAddress((void**)&WvLo, g_WvLo);
    cudaGetSymbolAddress((void**)&WoHi, g_WoHi);
    cudaGetSymbolAddress((void**)&WoLo, g_WoLo);
    cudaGetSymbolAddress((void**)&AHi, g_AHi);
    cudaGetSymbolAddress((void**)&ALo, g_ALo);
    cudaGetSymbolAddress((void**)&Qhp, g_Qh);
    cudaGetSymbolAddress((void**)&Qlp, g_Ql);
    cudaGetSymbolAddress((void**)&Khp, g_Kh);
    cudaGetSymbolAddress((void**)&Klp, g_Kl);
    cudaGetSymbolAddress((void**)&Vhp, g_Vh);
    cudaGetSymbolAddress((void**)&Vlp, g_Vl);

    cudaFuncSetAttribute(gemm_mma, cudaFuncAttributeMaxDynamicSharedMemorySize, SMEM_G);
    cudaFuncSetAttribute(gemm_kv,  cudaFuncAttributeMaxDynamicSharedMemorySize, SMEM_G);
    cudaFuncSetAttribute(attn_mma, cudaFuncAttributeMaxDynamicSharedMemorySize, ATTN_SMEM);

    // fp32 -> bf16 hi/lo splits
    {
        int n;
        n = QL * HDIM;
        cvt_split<<<n / 4 / 256, 256>>>((const float4*)hidden, (__nv_bfloat162*)hidHi, (__nv_bfloat162*)hidLo, n / 4);
        n = CTX * HDIM;
        cvt_split<<<n / 4 / 256, 256>>>((const float4*)target, (__nv_bfloat162*)tgtHi, (__nv_bfloat162*)tgtLo, n / 4);
        n = HDIM * HDIM;
        cvt_split<<<n / 4 / 256, 256>>>((const float4*)d_in[4], (__nv_bfloat162*)WqHi, (__nv_bfloat162*)WqLo, n / 4);
        n = NKV * HD * HDIM;
        cvt_split<<<n / 4 / 256, 256>>>((const float4*)d_in[5], (__nv_bfloat162*)WkHi, (__nv_bfloat162*)WkLo, n / 4);
        cvt_split<<<n / 4 / 256, 256>>>((const float4*)d_in[6], (__nv_bfloat162*)WvHi, (__nv_bfloat162*)WvLo, n / 4);
        n = HDIM * HDIM;
        cvt_split<<<n / 4 / 256, 256>>>((const float4*)d_in[7], (__nv_bfloat162*)WoHi, (__nv_bfloat162*)WoLo, n / 4);
    }

    // Projections (HMMA v2: 128x256 tiles, 3-stage)
    gemm_mma<<<dim3(HDIM / TN, QL / TM), 256, SMEM_G>>>(hidHi, hidLo, WqHi, WqLo, Qp, HDIM, HDIM, 0, 0);
    gemm_kv<<<dim3((NKV * HD) / TN, CTX / TM, 4), 256, SMEM_G>>>(Kp, Vp);

    // RoPE + splits for attention operands
    rope_q_split<<<(QL * NH * 64) / 256, 256>>>(Qp, cosb, sinb, Qhp, Qlp);
    rope_k_split<<<(NKV * KVLEN * 64) / 256, 256>>>(Kp, cosb, sinb, Khp, Klp);
    {
        int n = NKV * KVLEN * HD;
        cvt_split<<<n / 4 / 256, 256>>>((const float4*)Vp, (__nv_bfloat162*)Vhp, (__nv_bfloat162*)Vlp, n / 4);
    }

    // Flash attention (HMMA, 3-pass split); writes bf16 hi/lo for Wo
    attn_mma<<<dim3(QL / BQ, NH), 256, ATTN_SMEM>>>(Qhp, Qlp, AHi, ALo);

    // Output projection
    gemm_mma<<<dim3(HDIM / TN, QL / TM), 256, SMEM_G>>>(AHi, ALo, WoHi, WoLo, out, HDIM, HDIM, 0, 0);
}